// round 1
// baseline (speedup 1.0000x reference)
#include <cuda_runtime.h>
#include <math.h>

// Problem: out[b,c,:] = irfft( rfft(x[b,c,:], 16384) * Kspec[c,:], 16384 )[:8192]
// where Kspec = rfft( squash(smooth(kern[c,:])) , 16384) / 8192  (inverse FFT norm folded in)
//
// rfft(16384 real) computed as 8192-pt complex FFT of packed z[n] = x[2n] + i x[2n+1].
// FFT: Stockham radix-2, out-of-place ping-pong in shared memory, natural-order output.

#define N_FFT   8192
#define LOG_N   13
#define HALF_N  4096
#define NT      512
#define L_SEQ   8192
#define NCHAN   256
#define NROWS   2048           // 8 * 256
#define PI_F    3.14159265358979323846f

// Static device scratch (no allocation allowed)
__device__ float2 g_kspec[(size_t)NCHAN * (N_FFT + 1)];   // 256 x 8193 complex  (~16.8 MB)
__device__ float2 g_twid[HALF_N];                          // exp(-2*pi*i*j/8192), j in [0,4096)

__device__ __forceinline__ float2 cmul(float2 a, float2 b) {
    return make_float2(a.x * b.x - a.y * b.y, a.x * b.y + a.y * b.x);
}

// ---------------------------------------------------------------------------
// Stockham radix-2 FFT, 8192 points, NT threads per CTA.
// Each stage: for i in [0,4096): p=i>>st, q=i&(s-1), s=1<<st
//   a = src[i]; b = src[i+4096]; w = tw[p<<st] (conj if INV)
//   dst[q + (p<<(st+1))]     = a + b
//   dst[q + (p<<(st+1)) + s] = (a - b) * w
// After 13 stages result is in natural order. Returns the buffer holding it.
// ---------------------------------------------------------------------------
template <int INV>
__device__ float2* fft8192(float2* b0, float2* b1, int tid) {
    float2* src = b0;
    float2* dst = b1;
#pragma unroll 1
    for (int st = 0; st < LOG_N; st++) {
        const int s = 1 << st;
#pragma unroll
        for (int u = 0; u < HALF_N / NT; u++) {
            const int i = tid + (u << 9);            // NT = 512 = 1<<9
            const int p = i >> st;
            const int q = i & (s - 1);
            float2 a = src[i];
            float2 b = src[i + HALF_N];
            float2 w = g_twid[(i >> st) << st];      // p << st
            if (INV) w.y = -w.y;
            float2 sum = make_float2(a.x + b.x, a.y + b.y);
            float2 dif = make_float2(a.x - b.x, a.y - b.y);
            float2 bw  = cmul(dif, w);
            const int o = q + (p << (st + 1));
            dst[o]     = sum;
            dst[o + s] = bw;
        }
        __syncthreads();
        float2* t = src; src = dst; dst = t;
    }
    return src;
}

// ---------------------------------------------------------------------------
// Twiddle table init
// ---------------------------------------------------------------------------
__global__ void twid_init_kernel() {
    int j = blockIdx.x * blockDim.x + threadIdx.x;
    if (j < HALF_N) {
        double ang = -2.0 * 3.14159265358979323846 * (double)j / (double)N_FFT;
        g_twid[j] = make_float2((float)cos(ang), (float)sin(ang));
    }
}

// ---------------------------------------------------------------------------
// Per-channel kernel spectrum: smooth (reflect pad, W=7) -> soft-threshold
// -> rfft(16384) -> scale by 1/8192 -> store 8193 complex values.
// One CTA per channel. smem: 32KB raw + 2x64KB FFT buffers = 160KB.
// ---------------------------------------------------------------------------
__global__ void __launch_bounds__(NT, 1) kspec_kernel(const float* __restrict__ kern) {
    extern __shared__ char smraw[];
    float*  rk = (float*)smraw;                      // 8192 floats
    float2* b0 = (float2*)(smraw + L_SEQ * 4);       // 8192 complex
    float2* b1 = b0 + N_FFT;                         // 8192 complex

    const int c   = blockIdx.x;
    const int tid = threadIdx.x;
    const float* kr = kern + (size_t)c * L_SEQ;

    for (int i = tid; i < L_SEQ; i += NT) rk[i] = kr[i];
    __syncthreads();

    // smooth + squash, write directly into packed complex buffer (as floats)
    float* pk = (float*)b0;   // pk[j] = smoothed/squashed kernel sample j (packed layout)
    for (int i = tid; i < L_SEQ; i += NT) {
        float ssum = 0.f;
#pragma unroll
        for (int d = -3; d <= 3; d++) {
            int j = i + d;
            j = (j < 0) ? -j : j;
            j = (j > L_SEQ - 1) ? (2 * (L_SEQ - 1) - j) : j;
            ssum += rk[j];
        }
        float v = ssum * (1.0f / 7.0f);
        float a = fabsf(v) - 0.003f;
        v = (a > 0.f) ? copysignf(a, v) : 0.f;
        pk[i] = v;
    }
    for (int i = L_SEQ + tid; i < 2 * L_SEQ; i += NT) pk[i] = 0.f;
    __syncthreads();

    float2* zb = fft8192<0>(b0, b1, tid);

    // unpack real-FFT, scale by 1/8192, store to global
    float2* Kc = g_kspec + (size_t)c * (N_FFT + 1);
    const float inv = 1.0f / (float)N_FFT;
    for (int k = tid; k <= HALF_N; k += NT) {
        if (k == 0) {
            float2 Z0 = zb[0];
            Kc[0]     = make_float2((Z0.x + Z0.y) * inv, 0.f);
            Kc[N_FFT] = make_float2((Z0.x - Z0.y) * inv, 0.f);
        } else {
            float2 Zk = zb[k];
            float2 Zn = zb[N_FFT - k];
            float2 A = make_float2(0.5f * (Zk.x + Zn.x), 0.5f * (Zk.y - Zn.y));
            float2 D = make_float2(0.5f * (Zk.x - Zn.x), 0.5f * (Zk.y + Zn.y));
            float2 B = make_float2(D.y, -D.x);            // D / i
            float sv, cv;
            sincosf(-PI_F * (float)k * (1.0f / (float)N_FFT), &sv, &cv);
            float2 EB = make_float2(cv * B.x - sv * B.y, cv * B.y + sv * B.x);
            float2 Xk = make_float2(A.x + EB.x, A.y + EB.y);
            float2 Xn = make_float2(A.x - EB.x, -(A.y - EB.y));   // conj(A - E*B)
            Kc[k]         = make_float2(Xk.x * inv, Xk.y * inv);
            Kc[N_FFT - k] = make_float2(Xn.x * inv, Xn.y * inv);
        }
    }
}

// ---------------------------------------------------------------------------
// Main conv kernel: one CTA per (b,c) row. smem: 2x64KB = 128KB.
// load packed x -> fwd FFT -> (unpack * K * repack, in place) -> inv FFT -> store
// ---------------------------------------------------------------------------
__global__ void __launch_bounds__(NT, 1) conv_kernel(const float* __restrict__ x,
                                                     float* __restrict__ out) {
    extern __shared__ float2 sm2[];
    float2* b0 = sm2;
    float2* b1 = sm2 + N_FFT;

    const int row = blockIdx.x;          // b*256 + c
    const int c   = row & (NCHAN - 1);
    const int tid = threadIdx.x;

    // packed load: z[n] = x[2n] + i x[2n+1], zero pad upper half
    const float2* xr = (const float2*)(x + (size_t)row * L_SEQ);
    for (int i = tid; i < HALF_N; i += NT) b0[i] = xr[i];
    for (int i = HALF_N + tid; i < N_FFT; i += NT) b0[i] = make_float2(0.f, 0.f);
    __syncthreads();

    float2* zb = fft8192<0>(b0, b1, tid);

    // fused spectral pass: X = unpack(Z); Y = X*K; W = repack(Y); in place on zb
    const float2* Kc = g_kspec + (size_t)c * (N_FFT + 1);
    for (int k = tid; k <= HALF_N; k += NT) {
        if (k == 0) {
            float2 Z0 = zb[0];
            float X0 = Z0.x + Z0.y;                 // real
            float XN = Z0.x - Z0.y;                 // real
            float2 K0 = Kc[0];
            float2 KN = Kc[N_FFT];
            float2 Y0 = make_float2(X0 * K0.x, X0 * K0.y);
            float2 YN = make_float2(XN * KN.x, XN * KN.y);
            float2 Ay = make_float2(0.5f * (Y0.x + YN.x), 0.5f * (Y0.y - YN.y));
            float2 Dy = make_float2(0.5f * (Y0.x - YN.x), 0.5f * (Y0.y + YN.y));
            // E = 1 -> By = Dy ; W0 = Ay + i*By
            zb[0] = make_float2(Ay.x - Dy.y, Ay.y + Dy.x);
        } else {
            float2 Zk = zb[k];
            float2 Zn = zb[N_FFT - k];
            float2 A = make_float2(0.5f * (Zk.x + Zn.x), 0.5f * (Zk.y - Zn.y));
            float2 D = make_float2(0.5f * (Zk.x - Zn.x), 0.5f * (Zk.y + Zn.y));
            float2 B = make_float2(D.y, -D.x);
            float sv, cv;
            sincosf(-PI_F * (float)k * (1.0f / (float)N_FFT), &sv, &cv);
            float2 E  = make_float2(cv, sv);                  // e^{-i pi k / N}
            float2 EB = cmul(E, B);
            float2 Xk = make_float2(A.x + EB.x, A.y + EB.y);
            float2 Xn = make_float2(A.x - EB.x, -(A.y - EB.y));  // conj(A - E*B)
            float2 Yk = cmul(Xk, Kc[k]);
            float2 Yn = cmul(Xn, Kc[N_FFT - k]);
            float2 Ay = make_float2(0.5f * (Yk.x + Yn.x), 0.5f * (Yk.y - Yn.y));
            float2 Dy = make_float2(0.5f * (Yk.x - Yn.x), 0.5f * (Yk.y + Yn.y));
            float2 Ec = make_float2(cv, -sv);                 // conj(E)
            float2 By = cmul(Ec, Dy);
            // W[k]   = Ay + i*By ;  W[N-k] = conj(Ay) + i*conj(By)
            zb[k]         = make_float2(Ay.x - By.y,  Ay.y + By.x);
            zb[N_FFT - k] = make_float2(Ay.x + By.y, -Ay.y + By.x);
        }
    }
    __syncthreads();

    float2* other = (zb == b0) ? b1 : b0;
    float2* yb = fft8192<1>(zb, other, tid);   // 1/N scaling folded into Kspec

    // y[2n] = Re z[n], y[2n+1] = Im z[n]; need first 8192 samples = first 4096 complex
    float2* outr = (float2*)(out + (size_t)row * L_SEQ);
    for (int i = tid; i < HALF_N; i += NT) outr[i] = yb[i];
}

// ---------------------------------------------------------------------------
extern "C" void kernel_launch(void* const* d_in, const int* in_sizes, int n_in,
                              void* d_out, int out_size) {
    const float* x;
    const float* kern;
    if (in_sizes[0] == NROWS * L_SEQ) {   // 16,777,216 -> x first
        x    = (const float*)d_in[0];
        kern = (const float*)d_in[1];
    } else {
        x    = (const float*)d_in[1];
        kern = (const float*)d_in[0];
    }
    float* out = (float*)d_out;

    const int smem_kspec = L_SEQ * 4 + 2 * N_FFT * 8;   // 32KB + 128KB = 160KB
    const int smem_conv  = 2 * N_FFT * 8;               // 128KB
    cudaFuncSetAttribute(kspec_kernel, cudaFuncAttributeMaxDynamicSharedMemorySize, smem_kspec);
    cudaFuncSetAttribute(conv_kernel,  cudaFuncAttributeMaxDynamicSharedMemorySize, smem_conv);

    twid_init_kernel<<<(HALF_N + NT - 1) / NT, NT>>>();
    kspec_kernel<<<NCHAN, NT, smem_kspec>>>(kern);
    conv_kernel<<<NROWS, NT, smem_conv>>>(x, out);
}

// round 2
// speedup vs baseline: 1.3073x; 1.3073x over previous
#include <cuda_runtime.h>
#include <math.h>

// out[b,c,:] = irfft( rfft(x[b,c,:],16384) * Kspec[c,:], 16384 )[:8192]
// Kspec = rfft( squash(smooth(kern[c,:])), 16384 ) / 8192
// rfft(16384 real) via 8192-pt complex FFT of packed z[n] = x[2n] + i x[2n+1].
// FFT: Stockham radix-4 (6 stages) + radix-2 (1 stage), ping-pong in SMEM,
// skewed addressing (a + a/32) to kill scatter-write bank conflicts.

#define N_FFT   8192
#define HALF_N  4096
#define NT      512
#define L_SEQ   8192
#define NCHAN   256
#define NROWS   2048

#define BUF_PAD 8448                      // 8192 + 8192/32
#define SKEW(a) ((a) + ((a) >> 5))
#define TW_SZ   2048                      // max twiddle exponent p*s < 2048

// static device scratch (no allocation allowed)
__device__ float2 g_kspec[(size_t)NCHAN * (N_FFT + 1)];   // ~16.8 MB
__device__ float2 g_twid[TW_SZ];                          // W_8192^j, j in [0,2048)
__device__ float2 g_half[HALF_N + 1];                     // e^{-i pi k / 8192}, k in [0,4096]

__device__ __forceinline__ float2 cmul(float2 a, float2 b) {
    return make_float2(a.x * b.x - a.y * b.y, a.x * b.y + a.y * b.x);
}

// ---------------------------------------------------------------------------
// Stockham radix-4 FFT, 8192 pts. Buffers b0,b1 are SKEW-addressed (BUF_PAD).
// tw: 2048-entry smem twiddle table (forward twiddles). Result in b1 (natural order).
// ---------------------------------------------------------------------------
template <int INV>
__device__ float2* fft8192_r4(float2* __restrict__ b0, float2* __restrict__ b1,
                              const float2* __restrict__ tw, int tid) {
    float2* x = b0;
    float2* y = b1;
#pragma unroll 1
    for (int t = 0; t < 6; t++) {
        const int s = 1 << (2 * t);
#pragma unroll
        for (int u = 0; u < 4; u++) {
            const int i = tid + (u << 9);          // [0,2048)
            const int q = i & (s - 1);
            const int e = i & ~(s - 1);            // p*s  (twiddle exponent)
            float2 a = x[SKEW(i)];
            float2 b = x[SKEW(i + 2048)];
            float2 c = x[SKEW(i + 4096)];
            float2 d = x[SKEW(i + 6144)];
            float2 w1 = tw[e];
            if (INV) w1.y = -w1.y;
            float2 w2 = cmul(w1, w1);
            float2 w3 = cmul(w2, w1);
            float2 apc = make_float2(a.x + c.x, a.y + c.y);
            float2 amc = make_float2(a.x - c.x, a.y - c.y);
            float2 bpd = make_float2(b.x + d.x, b.y + d.y);
            float2 bmd = make_float2(b.x - d.x, b.y - d.y);
            float2 y0 = make_float2(apc.x + bpd.x, apc.y + bpd.y);
            float2 t2 = make_float2(apc.x - bpd.x, apc.y - bpd.y);
            float2 t1, t3;
            if (!INV) {
                t1 = make_float2(amc.x + bmd.y, amc.y - bmd.x);   // amc - j*bmd
                t3 = make_float2(amc.x - bmd.y, amc.y + bmd.x);   // amc + j*bmd
            } else {
                t1 = make_float2(amc.x - bmd.y, amc.y + bmd.x);
                t3 = make_float2(amc.x + bmd.y, amc.y - bmd.x);
            }
            const int o = q + (e << 2);            // q + 4*p*s
            y[SKEW(o)]         = y0;
            y[SKEW(o + s)]     = cmul(w1, t1);
            y[SKEW(o + 2 * s)] = cmul(w2, t2);
            y[SKEW(o + 3 * s)] = cmul(w3, t3);
        }
        __syncthreads();
        float2* tmp = x; x = y; y = tmp;
    }
    // final radix-2 stage, s = 4096, no twiddle
#pragma unroll
    for (int u = 0; u < 8; u++) {
        const int q = tid + (u << 9);
        float2 a = x[SKEW(q)];
        float2 b = x[SKEW(q + 4096)];
        y[SKEW(q)]        = make_float2(a.x + b.x, a.y + b.y);
        y[SKEW(q + 4096)] = make_float2(a.x - b.x, a.y - b.y);
    }
    __syncthreads();
    return y;    // = b1 (6 swaps + final write)
}

// ---------------------------------------------------------------------------
__global__ void twid_init_kernel() {
    int j = blockIdx.x * blockDim.x + threadIdx.x;
    if (j < TW_SZ) {
        float s, c;
        sincospif((float)j * (1.0f / 4096.0f), &s, &c);   // exact arg: j/2^12
        g_twid[j] = make_float2(c, -s);                    // e^{-2pi i j/8192}
    }
    if (j <= HALF_N) {
        float s, c;
        sincospif((float)j * (1.0f / 8192.0f), &s, &c);
        g_half[j] = make_float2(c, -s);                    // e^{-pi i j/8192}
    }
}

// ---------------------------------------------------------------------------
__device__ __forceinline__ float smooth_squash(const float* rk, int i) {
    float ssum = 0.f;
#pragma unroll
    for (int d = -3; d <= 3; d++) {
        int j = i + d;
        j = (j < 0) ? -j : j;
        j = (j > L_SEQ - 1) ? (2 * (L_SEQ - 1) - j) : j;
        ssum += rk[j];
    }
    float v = ssum * (1.0f / 7.0f);
    float a = fabsf(v) - 0.003f;
    return (a > 0.f) ? copysignf(a, v) : 0.f;
}

// smem layout (both kernels): b0[BUF_PAD] | b1[BUF_PAD] | tw[TW_SZ]
#define SMEM_BYTES ((2 * BUF_PAD + TW_SZ) * (int)sizeof(float2))

// ---------------------------------------------------------------------------
// Per-channel kernel spectrum. rk (raw kernel) overlays b1 (dead by stage 0 write).
// ---------------------------------------------------------------------------
__global__ void __launch_bounds__(NT, 1) kspec_kernel(const float* __restrict__ kern) {
    extern __shared__ float2 sm2[];
    float2* b0 = sm2;
    float2* b1 = sm2 + BUF_PAD;
    float2* tw = sm2 + 2 * BUF_PAD;
    float*  rk = (float*)b1;

    const int c   = blockIdx.x;
    const int tid = threadIdx.x;
    const float* kr = kern + (size_t)c * L_SEQ;

    for (int i = tid; i < L_SEQ; i += NT) rk[i] = kr[i];
    for (int i = tid; i < TW_SZ; i += NT) tw[i] = g_twid[i];
    __syncthreads();

    // smooth + squash -> packed complex in b0, zero-pad upper half
    for (int n = tid; n < HALF_N; n += NT) {
        float v0 = smooth_squash(rk, 2 * n);
        float v1 = smooth_squash(rk, 2 * n + 1);
        b0[SKEW(n)] = make_float2(v0, v1);
    }
    for (int n = HALF_N + tid; n < N_FFT; n += NT)
        b0[SKEW(n)] = make_float2(0.f, 0.f);
    __syncthreads();

    float2* zb = fft8192_r4<0>(b0, b1, tw, tid);

    // real-FFT unpack, scale 1/8192, store spectrum
    float2* Kc = g_kspec + (size_t)c * (N_FFT + 1);
    const float inv = 1.0f / (float)N_FFT;
    for (int k = tid; k <= HALF_N; k += NT) {
        if (k == 0) {
            float2 Z0 = zb[SKEW(0)];
            Kc[0]     = make_float2((Z0.x + Z0.y) * inv, 0.f);
            Kc[N_FFT] = make_float2((Z0.x - Z0.y) * inv, 0.f);
        } else {
            float2 Zk = zb[SKEW(k)];
            float2 Zn = zb[SKEW(N_FFT - k)];
            float2 A = make_float2(0.5f * (Zk.x + Zn.x), 0.5f * (Zk.y - Zn.y));
            float2 D = make_float2(0.5f * (Zk.x - Zn.x), 0.5f * (Zk.y + Zn.y));
            float2 B = make_float2(D.y, -D.x);            // D / i
            float2 E = g_half[k];
            float2 EB = cmul(E, B);
            float2 Xk = make_float2(A.x + EB.x, A.y + EB.y);
            float2 Xn = make_float2(A.x - EB.x, -(A.y - EB.y));
            Kc[k]         = make_float2(Xk.x * inv, Xk.y * inv);
            Kc[N_FFT - k] = make_float2(Xn.x * inv, Xn.y * inv);
        }
    }
}

// ---------------------------------------------------------------------------
// Main conv kernel: one CTA per (b,c) row.
// ---------------------------------------------------------------------------
__global__ void __launch_bounds__(NT, 1) conv_kernel(const float* __restrict__ x,
                                                     float* __restrict__ out) {
    extern __shared__ float2 sm2[];
    float2* b0 = sm2;
    float2* b1 = sm2 + BUF_PAD;
    float2* tw = sm2 + 2 * BUF_PAD;

    const int row = blockIdx.x;
    const int c   = row & (NCHAN - 1);
    const int tid = threadIdx.x;

    const float2* xr = (const float2*)(x + (size_t)row * L_SEQ);
    for (int i = tid; i < HALF_N; i += NT) b0[SKEW(i)] = xr[i];
    for (int i = HALF_N + tid; i < N_FFT; i += NT) b0[SKEW(i)] = make_float2(0.f, 0.f);
    for (int i = tid; i < TW_SZ; i += NT) tw[i] = g_twid[i];
    __syncthreads();

    float2* zb = fft8192_r4<0>(b0, b1, tw, tid);   // zb = b1

    // fused: unpack real spectrum, * K, repack — in place on zb
    const float2* Kc = g_kspec + (size_t)c * (N_FFT + 1);
    for (int k = tid; k <= HALF_N; k += NT) {
        if (k == 0) {
            float2 Z0 = zb[SKEW(0)];
            float X0 = Z0.x + Z0.y;
            float XN = Z0.x - Z0.y;
            float2 K0 = Kc[0];
            float2 KN = Kc[N_FFT];
            float2 Y0 = make_float2(X0 * K0.x, X0 * K0.y);
            float2 YN = make_float2(XN * KN.x, XN * KN.y);
            float2 Ay = make_float2(0.5f * (Y0.x + YN.x), 0.5f * (Y0.y - YN.y));
            float2 Dy = make_float2(0.5f * (Y0.x - YN.x), 0.5f * (Y0.y + YN.y));
            zb[SKEW(0)] = make_float2(Ay.x - Dy.y, Ay.y + Dy.x);
        } else {
            float2 Zk = zb[SKEW(k)];
            float2 Zn = zb[SKEW(N_FFT - k)];
            float2 A = make_float2(0.5f * (Zk.x + Zn.x), 0.5f * (Zk.y - Zn.y));
            float2 D = make_float2(0.5f * (Zk.x - Zn.x), 0.5f * (Zk.y + Zn.y));
            float2 B = make_float2(D.y, -D.x);
            float2 E = g_half[k];
            float2 EB = cmul(E, B);
            float2 Xk = make_float2(A.x + EB.x, A.y + EB.y);
            float2 Xn = make_float2(A.x - EB.x, -(A.y - EB.y));
            float2 Yk = cmul(Xk, Kc[k]);
            float2 Yn = cmul(Xn, Kc[N_FFT - k]);
            float2 Ay = make_float2(0.5f * (Yk.x + Yn.x), 0.5f * (Yk.y - Yn.y));
            float2 Dy = make_float2(0.5f * (Yk.x - Yn.x), 0.5f * (Yk.y + Yn.y));
            float2 Ec = make_float2(E.x, -E.y);
            float2 By = cmul(Ec, Dy);
            zb[SKEW(k)]         = make_float2(Ay.x - By.y,  Ay.y + By.x);
            zb[SKEW(N_FFT - k)] = make_float2(Ay.x + By.y, -Ay.y + By.x);
        }
    }
    __syncthreads();

    float2* yb = fft8192_r4<1>(b1, b0, tw, tid);   // yb = b0

    float2* outr = (float2*)(out + (size_t)row * L_SEQ);
    for (int i = tid; i < HALF_N; i += NT) outr[i] = yb[SKEW(i)];
}

// ---------------------------------------------------------------------------
extern "C" void kernel_launch(void* const* d_in, const int* in_sizes, int n_in,
                              void* d_out, int out_size) {
    const float* x;
    const float* kern;
    if (in_sizes[0] == NROWS * L_SEQ) {
        x    = (const float*)d_in[0];
        kern = (const float*)d_in[1];
    } else {
        x    = (const float*)d_in[1];
        kern = (const float*)d_in[0];
    }
    float* out = (float*)d_out;

    cudaFuncSetAttribute(kspec_kernel, cudaFuncAttributeMaxDynamicSharedMemorySize, SMEM_BYTES);
    cudaFuncSetAttribute(conv_kernel,  cudaFuncAttributeMaxDynamicSharedMemorySize, SMEM_BYTES);

    twid_init_kernel<<<(HALF_N + NT) / NT, NT>>>();
    kspec_kernel<<<NCHAN, NT, SMEM_BYTES>>>(kern);
    conv_kernel<<<NROWS, NT, SMEM_BYTES>>>(x, out);
}

// round 3
// speedup vs baseline: 1.3091x; 1.0014x over previous
#include <cuda_runtime.h>
#include <math.h>

// out[b,c,:] = irfft( rfft(x[b,c,:],16384) * Kspec[c,:], 16384 )[:8192]
// Kspec = rfft( squash(smooth(kern[c,:])), 16384 ) / 8192
// rfft(16384 real) via 8192-pt complex FFT of packed z[n] = x[2n] + i x[2n+1].
// FFT: Stockham radix-4 (6 stages) + radix-2 (1 stage), ping-pong in SMEM,
// skewed addressing (a + a/32) to kill scatter-write bank conflicts.

#define N_FFT   8192
#define HALF_N  4096
#define NT      512
#define L_SEQ   8192
#define NCHAN   256
#define NROWS   2048

#define BUF_PAD 8448                      // 8192 + 8192/32
#define SKEW(a) ((a) + ((a) >> 5))
#define TW_SZ   2048                      // max twiddle exponent p*s < 2048

// static device scratch (no allocation allowed)
__device__ float2 g_kspec[(size_t)NCHAN * (N_FFT + 1)];   // ~16.8 MB
__device__ float2 g_twid[TW_SZ];                          // W_8192^j, j in [0,2048)
__device__ float2 g_half[HALF_N + 1];                     // e^{-i pi k / 8192}, k in [0,4096]

__device__ __forceinline__ float2 cmul(float2 a, float2 b) {
    return make_float2(a.x * b.x - a.y * b.y, a.x * b.y + a.y * b.x);
}

// ---------------------------------------------------------------------------
// Stockham radix-4 FFT, 8192 pts. Buffers b0,b1 are SKEW-addressed (BUF_PAD).
// tw: 2048-entry smem twiddle table (forward twiddles). Result in b1 (natural order).
// ---------------------------------------------------------------------------
template <int INV>
__device__ float2* fft8192_r4(float2* __restrict__ b0, float2* __restrict__ b1,
                              const float2* __restrict__ tw, int tid) {
    float2* x = b0;
    float2* y = b1;
#pragma unroll 1
    for (int t = 0; t < 6; t++) {
        const int s = 1 << (2 * t);
#pragma unroll
        for (int u = 0; u < 4; u++) {
            const int i = tid + (u << 9);          // [0,2048)
            const int q = i & (s - 1);
            const int e = i & ~(s - 1);            // p*s  (twiddle exponent)
            float2 a = x[SKEW(i)];
            float2 b = x[SKEW(i + 2048)];
            float2 c = x[SKEW(i + 4096)];
            float2 d = x[SKEW(i + 6144)];
            float2 w1 = tw[e];
            if (INV) w1.y = -w1.y;
            float2 w2 = cmul(w1, w1);
            float2 w3 = cmul(w2, w1);
            float2 apc = make_float2(a.x + c.x, a.y + c.y);
            float2 amc = make_float2(a.x - c.x, a.y - c.y);
            float2 bpd = make_float2(b.x + d.x, b.y + d.y);
            float2 bmd = make_float2(b.x - d.x, b.y - d.y);
            float2 y0 = make_float2(apc.x + bpd.x, apc.y + bpd.y);
            float2 t2 = make_float2(apc.x - bpd.x, apc.y - bpd.y);
            float2 t1, t3;
            if (!INV) {
                t1 = make_float2(amc.x + bmd.y, amc.y - bmd.x);   // amc - j*bmd
                t3 = make_float2(amc.x - bmd.y, amc.y + bmd.x);   // amc + j*bmd
            } else {
                t1 = make_float2(amc.x - bmd.y, amc.y + bmd.x);
                t3 = make_float2(amc.x + bmd.y, amc.y - bmd.x);
            }
            const int o = q + (e << 2);            // q + 4*p*s
            y[SKEW(o)]         = y0;
            y[SKEW(o + s)]     = cmul(w1, t1);
            y[SKEW(o + 2 * s)] = cmul(w2, t2);
            y[SKEW(o + 3 * s)] = cmul(w3, t3);
        }
        __syncthreads();
        float2* tmp = x; x = y; y = tmp;
    }
    // final radix-2 stage, s = 4096, no twiddle
#pragma unroll
    for (int u = 0; u < 8; u++) {
        const int q = tid + (u << 9);
        float2 a = x[SKEW(q)];
        float2 b = x[SKEW(q + 4096)];
        y[SKEW(q)]        = make_float2(a.x + b.x, a.y + b.y);
        y[SKEW(q + 4096)] = make_float2(a.x - b.x, a.y - b.y);
    }
    __syncthreads();
    return y;    // = b1 (6 swaps + final write)
}

// ---------------------------------------------------------------------------
__global__ void twid_init_kernel() {
    int j = blockIdx.x * blockDim.x + threadIdx.x;
    if (j < TW_SZ) {
        float s, c;
        sincospif((float)j * (1.0f / 4096.0f), &s, &c);   // exact arg: j/2^12
        g_twid[j] = make_float2(c, -s);                    // e^{-2pi i j/8192}
    }
    if (j <= HALF_N) {
        float s, c;
        sincospif((float)j * (1.0f / 8192.0f), &s, &c);
        g_half[j] = make_float2(c, -s);                    // e^{-pi i j/8192}
    }
}

// ---------------------------------------------------------------------------
__device__ __forceinline__ float smooth_squash(const float* rk, int i) {
    float ssum = 0.f;
#pragma unroll
    for (int d = -3; d <= 3; d++) {
        int j = i + d;
        j = (j < 0) ? -j : j;
        j = (j > L_SEQ - 1) ? (2 * (L_SEQ - 1) - j) : j;
        ssum += rk[j];
    }
    float v = ssum * (1.0f / 7.0f);
    float a = fabsf(v) - 0.003f;
    return (a > 0.f) ? copysignf(a, v) : 0.f;
}

// smem layout (both kernels): b0[BUF_PAD] | b1[BUF_PAD] | tw[TW_SZ]
#define SMEM_BYTES ((2 * BUF_PAD + TW_SZ) * (int)sizeof(float2))

// ---------------------------------------------------------------------------
// Per-channel kernel spectrum. rk (raw kernel) overlays b1 (dead by stage 0 write).
// ---------------------------------------------------------------------------
__global__ void __launch_bounds__(NT, 1) kspec_kernel(const float* __restrict__ kern) {
    extern __shared__ float2 sm2[];
    float2* b0 = sm2;
    float2* b1 = sm2 + BUF_PAD;
    float2* tw = sm2 + 2 * BUF_PAD;
    float*  rk = (float*)b1;

    const int c   = blockIdx.x;
    const int tid = threadIdx.x;
    const float* kr = kern + (size_t)c * L_SEQ;

    for (int i = tid; i < L_SEQ; i += NT) rk[i] = kr[i];
    for (int i = tid; i < TW_SZ; i += NT) tw[i] = g_twid[i];
    __syncthreads();

    // smooth + squash -> packed complex in b0, zero-pad upper half
    for (int n = tid; n < HALF_N; n += NT) {
        float v0 = smooth_squash(rk, 2 * n);
        float v1 = smooth_squash(rk, 2 * n + 1);
        b0[SKEW(n)] = make_float2(v0, v1);
    }
    for (int n = HALF_N + tid; n < N_FFT; n += NT)
        b0[SKEW(n)] = make_float2(0.f, 0.f);
    __syncthreads();

    float2* zb = fft8192_r4<0>(b0, b1, tw, tid);

    // real-FFT unpack, scale 1/8192, store spectrum
    float2* Kc = g_kspec + (size_t)c * (N_FFT + 1);
    const float inv = 1.0f / (float)N_FFT;
    for (int k = tid; k <= HALF_N; k += NT) {
        if (k == 0) {
            float2 Z0 = zb[SKEW(0)];
            Kc[0]     = make_float2((Z0.x + Z0.y) * inv, 0.f);
            Kc[N_FFT] = make_float2((Z0.x - Z0.y) * inv, 0.f);
        } else {
            float2 Zk = zb[SKEW(k)];
            float2 Zn = zb[SKEW(N_FFT - k)];
            float2 A = make_float2(0.5f * (Zk.x + Zn.x), 0.5f * (Zk.y - Zn.y));
            float2 D = make_float2(0.5f * (Zk.x - Zn.x), 0.5f * (Zk.y + Zn.y));
            float2 B = make_float2(D.y, -D.x);            // D / i
            float2 E = g_half[k];
            float2 EB = cmul(E, B);
            float2 Xk = make_float2(A.x + EB.x, A.y + EB.y);
            float2 Xn = make_float2(A.x - EB.x, -(A.y - EB.y));
            Kc[k]         = make_float2(Xk.x * inv, Xk.y * inv);
            Kc[N_FFT - k] = make_float2(Xn.x * inv, Xn.y * inv);
        }
    }
}

// ---------------------------------------------------------------------------
// Main conv kernel: one CTA per (b,c) row.
// ---------------------------------------------------------------------------
__global__ void __launch_bounds__(NT, 1) conv_kernel(const float* __restrict__ x,
                                                     float* __restrict__ out) {
    extern __shared__ float2 sm2[];
    float2* b0 = sm2;
    float2* b1 = sm2 + BUF_PAD;
    float2* tw = sm2 + 2 * BUF_PAD;

    const int row = blockIdx.x;
    const int c   = row & (NCHAN - 1);
    const int tid = threadIdx.x;

    const float2* xr = (const float2*)(x + (size_t)row * L_SEQ);
    for (int i = tid; i < HALF_N; i += NT) b0[SKEW(i)] = xr[i];
    for (int i = HALF_N + tid; i < N_FFT; i += NT) b0[SKEW(i)] = make_float2(0.f, 0.f);
    for (int i = tid; i < TW_SZ; i += NT) tw[i] = g_twid[i];
    __syncthreads();

    float2* zb = fft8192_r4<0>(b0, b1, tw, tid);   // zb = b1

    // fused: unpack real spectrum, * K, repack — in place on zb
    const float2* Kc = g_kspec + (size_t)c * (N_FFT + 1);
    for (int k = tid; k <= HALF_N; k += NT) {
        if (k == 0) {
            float2 Z0 = zb[SKEW(0)];
            float X0 = Z0.x + Z0.y;
            float XN = Z0.x - Z0.y;
            float2 K0 = Kc[0];
            float2 KN = Kc[N_FFT];
            float2 Y0 = make_float2(X0 * K0.x, X0 * K0.y);
            float2 YN = make_float2(XN * KN.x, XN * KN.y);
            float2 Ay = make_float2(0.5f * (Y0.x + YN.x), 0.5f * (Y0.y - YN.y));
            float2 Dy = make_float2(0.5f * (Y0.x - YN.x), 0.5f * (Y0.y + YN.y));
            zb[SKEW(0)] = make_float2(Ay.x - Dy.y, Ay.y + Dy.x);
        } else {
            float2 Zk = zb[SKEW(k)];
            float2 Zn = zb[SKEW(N_FFT - k)];
            float2 A = make_float2(0.5f * (Zk.x + Zn.x), 0.5f * (Zk.y - Zn.y));
            float2 D = make_float2(0.5f * (Zk.x - Zn.x), 0.5f * (Zk.y + Zn.y));
            float2 B = make_float2(D.y, -D.x);
            float2 E = g_half[k];
            float2 EB = cmul(E, B);
            float2 Xk = make_float2(A.x + EB.x, A.y + EB.y);
            float2 Xn = make_float2(A.x - EB.x, -(A.y - EB.y));
            float2 Yk = cmul(Xk, Kc[k]);
            float2 Yn = cmul(Xn, Kc[N_FFT - k]);
            float2 Ay = make_float2(0.5f * (Yk.x + Yn.x), 0.5f * (Yk.y - Yn.y));
            float2 Dy = make_float2(0.5f * (Yk.x - Yn.x), 0.5f * (Yk.y + Yn.y));
            float2 Ec = make_float2(E.x, -E.y);
            float2 By = cmul(Ec, Dy);
            zb[SKEW(k)]         = make_float2(Ay.x - By.y,  Ay.y + By.x);
            zb[SKEW(N_FFT - k)] = make_float2(Ay.x + By.y, -Ay.y + By.x);
        }
    }
    __syncthreads();

    float2* yb = fft8192_r4<1>(b1, b0, tw, tid);   // yb = b0

    float2* outr = (float2*)(out + (size_t)row * L_SEQ);
    for (int i = tid; i < HALF_N; i += NT) outr[i] = yb[SKEW(i)];
}

// ---------------------------------------------------------------------------
extern "C" void kernel_launch(void* const* d_in, const int* in_sizes, int n_in,
                              void* d_out, int out_size) {
    const float* x;
    const float* kern;
    if (in_sizes[0] == NROWS * L_SEQ) {
        x    = (const float*)d_in[0];
        kern = (const float*)d_in[1];
    } else {
        x    = (const float*)d_in[1];
        kern = (const float*)d_in[0];
    }
    float* out = (float*)d_out;

    cudaFuncSetAttribute(kspec_kernel, cudaFuncAttributeMaxDynamicSharedMemorySize, SMEM_BYTES);
    cudaFuncSetAttribute(conv_kernel,  cudaFuncAttributeMaxDynamicSharedMemorySize, SMEM_BYTES);

    twid_init_kernel<<<(HALF_N + NT) / NT, NT>>>();
    kspec_kernel<<<NCHAN, NT, SMEM_BYTES>>>(kern);
    conv_kernel<<<NROWS, NT, SMEM_BYTES>>>(x, out);
}

// round 4
// speedup vs baseline: 1.6021x; 1.2238x over previous
#include <cuda_runtime.h>
#include <math.h>

// out[b,c,:] = irfft( rfft(x[b,c,:],16384) * Kspec[c,:], 16384 )[:8192]
// Kspec = rfft( squash(smooth(kern[c,:])), 16384 ) / 8192
// rfft(16384) via 8192-pt complex FFT of z[n] = x[2n] + i x[2n+1].
// Stockham radix-4 x6 + radix-2, ping-pong in SMEM, skew a+(a>>4).

#define N_FFT   8192
#define HALF_N  4096
#define NT      1024
#define L_SEQ   8192
#define NCHAN   256
#define NROWS   2048

#define BUF_PAD 8704                      // 8192 + 8192/16
#define SKEW(a) ((a) + ((a) >> 4))
#define TW_SZ   2048

__device__ float2 g_kspec[(size_t)NCHAN * (N_FFT + 1)];

__device__ __forceinline__ float2 cmul(float2 a, float2 b) {
    return make_float2(a.x * b.x - a.y * b.y, a.x * b.y + a.y * b.x);
}

// ---------------------------------------------------------------------------
template <int INV>
__device__ float2* fft8192_r4(float2* __restrict__ b0, float2* __restrict__ b1,
                              const float2* __restrict__ tw, int tid) {
    float2* x = b0;
    float2* y = b1;
#pragma unroll 1
    for (int t = 0; t < 6; t++) {
        const int s = 1 << (2 * t);
#pragma unroll
        for (int u = 0; u < 2; u++) {
            const int i = tid + (u << 10);         // [0,2048)
            const int q = i & (s - 1);
            const int e = i & ~(s - 1);            // p*s
            float2 a = x[SKEW(i)];
            float2 b = x[SKEW(i + 2048)];
            float2 c = x[SKEW(i + 4096)];
            float2 d = x[SKEW(i + 6144)];
            float2 w1 = tw[e];
            if (INV) w1.y = -w1.y;
            float2 w2 = cmul(w1, w1);
            float2 w3 = cmul(w2, w1);
            float2 apc = make_float2(a.x + c.x, a.y + c.y);
            float2 amc = make_float2(a.x - c.x, a.y - c.y);
            float2 bpd = make_float2(b.x + d.x, b.y + d.y);
            float2 bmd = make_float2(b.x - d.x, b.y - d.y);
            float2 y0 = make_float2(apc.x + bpd.x, apc.y + bpd.y);
            float2 t2 = make_float2(apc.x - bpd.x, apc.y - bpd.y);
            float2 t1, t3;
            if (!INV) {
                t1 = make_float2(amc.x + bmd.y, amc.y - bmd.x);
                t3 = make_float2(amc.x - bmd.y, amc.y + bmd.x);
            } else {
                t1 = make_float2(amc.x - bmd.y, amc.y + bmd.x);
                t3 = make_float2(amc.x + bmd.y, amc.y - bmd.x);
            }
            const int o = q + (e << 2);
            y[SKEW(o)]         = y0;
            y[SKEW(o + s)]     = cmul(w1, t1);
            y[SKEW(o + 2 * s)] = cmul(w2, t2);
            y[SKEW(o + 3 * s)] = cmul(w3, t3);
        }
        __syncthreads();
        float2* tmp = x; x = y; y = tmp;
    }
#pragma unroll
    for (int u = 0; u < 4; u++) {
        const int q = tid + (u << 10);
        float2 a = x[SKEW(q)];
        float2 b = x[SKEW(q + 4096)];
        y[SKEW(q)]        = make_float2(a.x + b.x, a.y + b.y);
        y[SKEW(q + 4096)] = make_float2(a.x - b.x, a.y - b.y);
    }
    __syncthreads();
    return y;
}

// per-CTA twiddle table build: W_8192^j = e^{-i pi j/4096}, j in [0,2048)
__device__ __forceinline__ void fill_tw(float2* tw, int tid) {
#pragma unroll
    for (int j = tid; j < TW_SZ; j += NT) {
        float s, c;
        sincospif((float)j * (1.0f / 4096.0f), &s, &c);
        tw[j] = make_float2(c, -s);
    }
}

__device__ __forceinline__ float2 efac(int k) {     // e^{-i pi k/8192}
    float s, c;
    sincospif((float)k * (1.0f / 8192.0f), &s, &c);
    return make_float2(c, -s);
}

__device__ __forceinline__ float smooth_squash(const float* rk, int i) {
    float ssum = 0.f;
#pragma unroll
    for (int d = -3; d <= 3; d++) {
        int j = i + d;
        j = (j < 0) ? -j : j;
        j = (j > L_SEQ - 1) ? (2 * (L_SEQ - 1) - j) : j;
        ssum += rk[j];
    }
    float v = ssum * (1.0f / 7.0f);
    float a = fabsf(v) - 0.003f;
    return (a > 0.f) ? copysignf(a, v) : 0.f;
}

// smem: b0[BUF_PAD] | b1[BUF_PAD] | tw[TW_SZ]
#define SMEM_BYTES ((2 * BUF_PAD + TW_SZ) * (int)sizeof(float2))

// ---------------------------------------------------------------------------
__global__ void __launch_bounds__(NT, 1) kspec_kernel(const float* __restrict__ kern) {
    extern __shared__ float2 sm2[];
    float2* b0 = sm2;
    float2* b1 = sm2 + BUF_PAD;
    float2* tw = sm2 + 2 * BUF_PAD;
    float*  rk = (float*)b1;

    const int c   = blockIdx.x;
    const int tid = threadIdx.x;
    const float* kr = kern + (size_t)c * L_SEQ;

    for (int i = tid; i < L_SEQ; i += NT) rk[i] = kr[i];
    fill_tw(tw, tid);
    __syncthreads();

    for (int n = tid; n < HALF_N; n += NT) {
        float v0 = smooth_squash(rk, 2 * n);
        float v1 = smooth_squash(rk, 2 * n + 1);
        b0[SKEW(n)] = make_float2(v0, v1);
    }
    for (int n = HALF_N + tid; n < N_FFT; n += NT)
        b0[SKEW(n)] = make_float2(0.f, 0.f);
    __syncthreads();

    float2* zb = fft8192_r4<0>(b0, b1, tw, tid);

    float2* Kc = g_kspec + (size_t)c * (N_FFT + 1);
    const float inv = 1.0f / (float)N_FFT;
    for (int k = tid; k <= HALF_N; k += NT) {
        if (k == 0) {
            float2 Z0 = zb[SKEW(0)];
            Kc[0]     = make_float2((Z0.x + Z0.y) * inv, 0.f);
            Kc[N_FFT] = make_float2((Z0.x - Z0.y) * inv, 0.f);
        } else {
            float2 Zk = zb[SKEW(k)];
            float2 Zn = zb[SKEW(N_FFT - k)];
            float2 A = make_float2(0.5f * (Zk.x + Zn.x), 0.5f * (Zk.y - Zn.y));
            float2 D = make_float2(0.5f * (Zk.x - Zn.x), 0.5f * (Zk.y + Zn.y));
            float2 B = make_float2(D.y, -D.x);
            float2 E = efac(k);
            float2 EB = cmul(E, B);
            float2 Xk = make_float2(A.x + EB.x, A.y + EB.y);
            float2 Xn = make_float2(A.x - EB.x, -(A.y - EB.y));
            Kc[k]         = make_float2(Xk.x * inv, Xk.y * inv);
            Kc[N_FFT - k] = make_float2(Xn.x * inv, Xn.y * inv);
        }
    }
}

// ---------------------------------------------------------------------------
__global__ void __launch_bounds__(NT, 1) conv_kernel(const float* __restrict__ x,
                                                     float* __restrict__ out) {
    extern __shared__ float2 sm2[];
    float2* b0 = sm2;
    float2* b1 = sm2 + BUF_PAD;
    float2* tw = sm2 + 2 * BUF_PAD;

    const int row = blockIdx.x;
    const int c   = row & (NCHAN - 1);
    const int tid = threadIdx.x;

    const float2* xr = (const float2*)(x + (size_t)row * L_SEQ);
    for (int i = tid; i < HALF_N; i += NT) b0[SKEW(i)] = xr[i];
    for (int i = HALF_N + tid; i < N_FFT; i += NT) b0[SKEW(i)] = make_float2(0.f, 0.f);
    fill_tw(tw, tid);
    __syncthreads();

    float2* zb = fft8192_r4<0>(b0, b1, tw, tid);

    const float2* Kc = g_kspec + (size_t)c * (N_FFT + 1);
    for (int k = tid; k <= HALF_N; k += NT) {
        if (k == 0) {
            float2 Z0 = zb[SKEW(0)];
            float X0 = Z0.x + Z0.y;
            float XN = Z0.x - Z0.y;
            float2 K0 = Kc[0];
            float2 KN = Kc[N_FFT];
            float2 Y0 = make_float2(X0 * K0.x, X0 * K0.y);
            float2 YN = make_float2(XN * KN.x, XN * KN.y);
            float2 Ay = make_float2(0.5f * (Y0.x + YN.x), 0.5f * (Y0.y - YN.y));
            float2 Dy = make_float2(0.5f * (Y0.x - YN.x), 0.5f * (Y0.y + YN.y));
            zb[SKEW(0)] = make_float2(Ay.x - Dy.y, Ay.y + Dy.x);
        } else {
            float2 Zk = zb[SKEW(k)];
            float2 Zn = zb[SKEW(N_FFT - k)];
            float2 A = make_float2(0.5f * (Zk.x + Zn.x), 0.5f * (Zk.y - Zn.y));
            float2 D = make_float2(0.5f * (Zk.x - Zn.x), 0.5f * (Zk.y + Zn.y));
            float2 B = make_float2(D.y, -D.x);
            float2 E = efac(k);
            float2 EB = cmul(E, B);
            float2 Xk = make_float2(A.x + EB.x, A.y + EB.y);
            float2 Xn = make_float2(A.x - EB.x, -(A.y - EB.y));
            float2 Yk = cmul(Xk, Kc[k]);
            float2 Yn = cmul(Xn, Kc[N_FFT - k]);
            float2 Ay = make_float2(0.5f * (Yk.x + Yn.x), 0.5f * (Yk.y - Yn.y));
            float2 Dy = make_float2(0.5f * (Yk.x - Yn.x), 0.5f * (Yk.y + Yn.y));
            float2 Ec = make_float2(E.x, -E.y);
            float2 By = cmul(Ec, Dy);
            zb[SKEW(k)]         = make_float2(Ay.x - By.y,  Ay.y + By.x);
            zb[SKEW(N_FFT - k)] = make_float2(Ay.x + By.y, -Ay.y + By.x);
        }
    }
    __syncthreads();

    float2* yb = fft8192_r4<1>(b1, b0, tw, tid);

    float2* outr = (float2*)(out + (size_t)row * L_SEQ);
    for (int i = tid; i < HALF_N; i += NT) outr[i] = yb[SKEW(i)];
}

// ---------------------------------------------------------------------------
extern "C" void kernel_launch(void* const* d_in, const int* in_sizes, int n_in,
                              void* d_out, int out_size) {
    const float* x;
    const float* kern;
    if (in_sizes[0] == NROWS * L_SEQ) {
        x    = (const float*)d_in[0];
        kern = (const float*)d_in[1];
    } else {
        x    = (const float*)d_in[1];
        kern = (const float*)d_in[0];
    }
    float* out = (float*)d_out;

    cudaFuncSetAttribute(kspec_kernel, cudaFuncAttributeMaxDynamicSharedMemorySize, SMEM_BYTES);
    cudaFuncSetAttribute(conv_kernel,  cudaFuncAttributeMaxDynamicSharedMemorySize, SMEM_BYTES);

    kspec_kernel<<<NCHAN, NT, SMEM_BYTES>>>(kern);
    conv_kernel<<<NROWS, NT, SMEM_BYTES>>>(x, out);
}

// round 5
// speedup vs baseline: 1.9152x; 1.1954x over previous
#include <cuda_runtime.h>
#include <math.h>

// out[b,c,:] = irfft( rfft(x,16384) * Kspec[c], 16384 )[:8192]
// rfft(16384) via 8192-pt complex FFT of z[n] = x[2n] + i x[2n+1].
// Stockham radix-8 x4 + radix-2, ping-pong SMEM, skew a+(a>>4).

#define N_FFT   8192
#define HALF_N  4096
#define NT      1024
#define L_SEQ   8192
#define NCHAN   256
#define NROWS   2048

#define BUF_PAD 8704
#define SKEW(a) ((a) + ((a) >> 4))
#define TWT     1024

__device__ float2 g_kspec[(size_t)NCHAN * (N_FFT + 1)];

__device__ __forceinline__ float2 cmul(float2 a, float2 b) {
    return make_float2(a.x * b.x - a.y * b.y, a.x * b.y + a.y * b.x);
}
__device__ __forceinline__ float2 cadd(float2 a, float2 b) { return make_float2(a.x + b.x, a.y + b.y); }
__device__ __forceinline__ float2 csub(float2 a, float2 b) { return make_float2(a.x - b.x, a.y - b.y); }

// in-place 8-point DFT (forward: W_8 = e^{-2pi i/8}; INV: conjugate)
template <int INV>
__device__ __forceinline__ void dft8(float2* v) {
    const float u = 0.70710678118654752f;
    float2 apc = cadd(v[0], v[4]), amc = csub(v[0], v[4]);
    float2 bpd = cadd(v[2], v[6]), bmd = csub(v[2], v[6]);
    float2 E0 = cadd(apc, bpd), E2 = csub(apc, bpd), E1, E3;
    if (!INV) { E1 = make_float2(amc.x + bmd.y, amc.y - bmd.x); E3 = make_float2(amc.x - bmd.y, amc.y + bmd.x); }
    else      { E1 = make_float2(amc.x - bmd.y, amc.y + bmd.x); E3 = make_float2(amc.x + bmd.y, amc.y - bmd.x); }
    apc = cadd(v[1], v[5]); amc = csub(v[1], v[5]);
    bpd = cadd(v[3], v[7]); bmd = csub(v[3], v[7]);
    float2 O0 = cadd(apc, bpd), O2 = csub(apc, bpd), O1, O3;
    if (!INV) { O1 = make_float2(amc.x + bmd.y, amc.y - bmd.x); O3 = make_float2(amc.x - bmd.y, amc.y + bmd.x); }
    else      { O1 = make_float2(amc.x - bmd.y, amc.y + bmd.x); O3 = make_float2(amc.x + bmd.y, amc.y - bmd.x); }
    float2 T1, T2, T3;
    if (!INV) {
        T1 = make_float2(u * (O1.x + O1.y), u * (O1.y - O1.x));
        T2 = make_float2(O2.y, -O2.x);
        T3 = make_float2(u * (O3.y - O3.x), -u * (O3.x + O3.y));
    } else {
        T1 = make_float2(u * (O1.x - O1.y), u * (O1.x + O1.y));
        T2 = make_float2(-O2.y, O2.x);
        T3 = make_float2(-u * (O3.x + O3.y), u * (O3.x - O3.y));
    }
    v[0] = cadd(E0, O0); v[4] = csub(E0, O0);
    v[1] = cadd(E1, T1); v[5] = csub(E1, T1);
    v[2] = cadd(E2, T2); v[6] = csub(E2, T2);
    v[3] = cadd(E3, T3); v[7] = csub(E3, T3);
}

// ---------------------------------------------------------------------------
// 8192-pt FFT: 4 radix-8 stages (s=1,8,64,512) + radix-2 finisher (s=4096).
// tw1[e]=W^e, tw2[e]=W^{2e}, tw4[e]=W^{4e}, e in [0,1024).
// Returns the buffer holding the natural-order result (= second arg).
// ---------------------------------------------------------------------------
template <int INV>
__device__ float2* fft8192_r8(float2* __restrict__ b0, float2* __restrict__ b1,
                              const float2* __restrict__ tw1,
                              const float2* __restrict__ tw2,
                              const float2* __restrict__ tw4, int tid) {
    float2* x = b0;
    float2* y = b1;
    int s = 1;
#pragma unroll 1
    for (int t = 0; t < 4; t++) {
        const int q = tid & (s - 1);
        const int e = tid - q;
        float2 v[8];
#pragma unroll
        for (int j = 0; j < 8; j++) v[j] = x[SKEW(tid + (j << 10))];
        dft8<INV>(v);
        float2 w1 = tw1[e], w2 = tw2[e], w4 = tw4[e];
        if (INV) { w1.y = -w1.y; w2.y = -w2.y; w4.y = -w4.y; }
        const int o = q + (e << 3);
        y[SKEW(o)]         = v[0];
        y[SKEW(o + s)]     = cmul(w1, v[1]);
        y[SKEW(o + 2*s)]   = cmul(w2, v[2]);
        float2 w3 = cmul(w1, w2);
        y[SKEW(o + 3*s)]   = cmul(w3, v[3]);
        y[SKEW(o + 4*s)]   = cmul(w4, v[4]);
        y[SKEW(o + 5*s)]   = cmul(cmul(w1, w4), v[5]);
        y[SKEW(o + 6*s)]   = cmul(cmul(w2, w4), v[6]);
        y[SKEW(o + 7*s)]   = cmul(cmul(w3, w4), v[7]);
        __syncthreads();
        float2* tmp = x; x = y; y = tmp;
        s <<= 3;
    }
#pragma unroll
    for (int u2 = 0; u2 < 4; u2++) {
        const int q = tid + (u2 << 10);
        float2 a = x[SKEW(q)];
        float2 b = x[SKEW(q + 4096)];
        y[SKEW(q)]        = cadd(a, b);
        y[SKEW(q + 4096)] = csub(a, b);
    }
    __syncthreads();
    return y;
}

__device__ __forceinline__ void fill_tw(float2* tw1, float2* tw2, float2* tw4, int tid) {
#pragma unroll 1
    for (int j = tid; j < TWT; j += NT) {
        float s, c;
        sincospif((float)j * (1.0f / 4096.0f), &s, &c);
        tw1[j] = make_float2(c, -s);
        sincospif((float)j * (1.0f / 2048.0f), &s, &c);
        tw2[j] = make_float2(c, -s);
        sincospif((float)j * (1.0f / 1024.0f), &s, &c);
        tw4[j] = make_float2(c, -s);
    }
}

__device__ __forceinline__ float2 efac(int k) {   // e^{-i pi k/8192}
    float s, c;
    sincospif((float)k * (1.0f / 8192.0f), &s, &c);
    return make_float2(c, -s);
}

__device__ __forceinline__ float smooth_squash(const float* rk, int i) {
    float ssum = 0.f;
#pragma unroll
    for (int d = -3; d <= 3; d++) {
        int j = i + d;
        j = (j < 0) ? -j : j;
        j = (j > L_SEQ - 1) ? (2 * (L_SEQ - 1) - j) : j;
        ssum += rk[j];
    }
    float v = ssum * (1.0f / 7.0f);
    float a = fabsf(v) - 0.003f;
    return (a > 0.f) ? copysignf(a, v) : 0.f;
}

// smem: b0[BUF_PAD] | b1[BUF_PAD] | tw1[TWT] | tw2[TWT] | tw4[TWT]
#define SMEM_BYTES ((2 * BUF_PAD + 3 * TWT) * (int)sizeof(float2))

// ---------------------------------------------------------------------------
__global__ void __launch_bounds__(NT, 1) kspec_kernel(const float* __restrict__ kern) {
    extern __shared__ float2 sm2[];
    float2* b0  = sm2;
    float2* b1  = sm2 + BUF_PAD;
    float2* tw1 = sm2 + 2 * BUF_PAD;
    float2* tw2 = tw1 + TWT;
    float2* tw4 = tw2 + TWT;
    float*  rk  = (float*)b1;

    const int c   = blockIdx.x;
    const int tid = threadIdx.x;
    const float* kr = kern + (size_t)c * L_SEQ;

    for (int i = tid; i < L_SEQ; i += NT) rk[i] = kr[i];
    fill_tw(tw1, tw2, tw4, tid);
    __syncthreads();

    for (int n = tid; n < HALF_N; n += NT) {
        float v0 = smooth_squash(rk, 2 * n);
        float v1 = smooth_squash(rk, 2 * n + 1);
        b0[SKEW(n)] = make_float2(v0, v1);
    }
    for (int n = HALF_N + tid; n < N_FFT; n += NT)
        b0[SKEW(n)] = make_float2(0.f, 0.f);
    __syncthreads();

    float2* zb = fft8192_r8<0>(b0, b1, tw1, tw2, tw4, tid);

    float2* Kc = g_kspec + (size_t)c * (N_FFT + 1);
    const float inv = 1.0f / (float)N_FFT;
    for (int k = tid; k <= HALF_N; k += NT) {
        if (k == 0) {
            float2 Z0 = zb[SKEW(0)];
            Kc[0]     = make_float2((Z0.x + Z0.y) * inv, 0.f);
            Kc[N_FFT] = make_float2((Z0.x - Z0.y) * inv, 0.f);
        } else {
            float2 Zk = zb[SKEW(k)];
            float2 Zn = zb[SKEW(N_FFT - k)];
            float2 A = make_float2(0.5f * (Zk.x + Zn.x), 0.5f * (Zk.y - Zn.y));
            float2 D = make_float2(0.5f * (Zk.x - Zn.x), 0.5f * (Zk.y + Zn.y));
            float2 B = make_float2(D.y, -D.x);
            float2 E = efac(k);
            float2 EB = cmul(E, B);
            float2 Xk = make_float2(A.x + EB.x, A.y + EB.y);
            float2 Xn = make_float2(A.x - EB.x, -(A.y - EB.y));
            Kc[k]         = make_float2(Xk.x * inv, Xk.y * inv);
            Kc[N_FFT - k] = make_float2(Xn.x * inv, Xn.y * inv);
        }
    }
}

// ---------------------------------------------------------------------------
__global__ void __launch_bounds__(NT, 1) conv_kernel(const float* __restrict__ x,
                                                     float* __restrict__ out) {
    extern __shared__ float2 sm2[];
    float2* b0  = sm2;
    float2* b1  = sm2 + BUF_PAD;
    float2* tw1 = sm2 + 2 * BUF_PAD;
    float2* tw2 = tw1 + TWT;
    float2* tw4 = tw2 + TWT;

    const int row = blockIdx.x;
    const int c   = row & (NCHAN - 1);
    const int tid = threadIdx.x;

    const float2* xr = (const float2*)(x + (size_t)row * L_SEQ);
    for (int i = tid; i < HALF_N; i += NT) b0[SKEW(i)] = xr[i];
    for (int i = HALF_N + tid; i < N_FFT; i += NT) b0[SKEW(i)] = make_float2(0.f, 0.f);
    fill_tw(tw1, tw2, tw4, tid);
    __syncthreads();

    float2* zb = fft8192_r8<0>(b0, b1, tw1, tw2, tw4, tid);

    const float2* Kc = g_kspec + (size_t)c * (N_FFT + 1);
    for (int k = tid; k <= HALF_N; k += NT) {
        if (k == 0) {
            float2 Z0 = zb[SKEW(0)];
            float X0 = Z0.x + Z0.y;
            float XN = Z0.x - Z0.y;
            float2 K0 = Kc[0];
            float2 KN = Kc[N_FFT];
            float2 Y0 = make_float2(X0 * K0.x, X0 * K0.y);
            float2 YN = make_float2(XN * KN.x, XN * KN.y);
            float2 Ay = make_float2(0.5f * (Y0.x + YN.x), 0.5f * (Y0.y - YN.y));
            float2 Dy = make_float2(0.5f * (Y0.x - YN.x), 0.5f * (Y0.y + YN.y));
            zb[SKEW(0)] = make_float2(Ay.x - Dy.y, Ay.y + Dy.x);
        } else {
            float2 Zk = zb[SKEW(k)];
            float2 Zn = zb[SKEW(N_FFT - k)];
            float2 A = make_float2(0.5f * (Zk.x + Zn.x), 0.5f * (Zk.y - Zn.y));
            float2 D = make_float2(0.5f * (Zk.x - Zn.x), 0.5f * (Zk.y + Zn.y));
            float2 B = make_float2(D.y, -D.x);
            float2 E = efac(k);
            float2 EB = cmul(E, B);
            float2 Xk = make_float2(A.x + EB.x, A.y + EB.y);
            float2 Xn = make_float2(A.x - EB.x, -(A.y - EB.y));
            float2 Yk = cmul(Xk, Kc[k]);
            float2 Yn = cmul(Xn, Kc[N_FFT - k]);
            float2 Ay = make_float2(0.5f * (Yk.x + Yn.x), 0.5f * (Yk.y - Yn.y));
            float2 Dy = make_float2(0.5f * (Yk.x - Yn.x), 0.5f * (Yk.y + Yn.y));
            float2 Ec = make_float2(E.x, -E.y);
            float2 By = cmul(Ec, Dy);
            zb[SKEW(k)]         = make_float2(Ay.x - By.y,  Ay.y + By.x);
            zb[SKEW(N_FFT - k)] = make_float2(Ay.x + By.y, -Ay.y + By.x);
        }
    }
    __syncthreads();

    float2* yb = fft8192_r8<1>(b1, b0, tw1, tw2, tw4, tid);

    float2* outr = (float2*)(out + (size_t)row * L_SEQ);
    for (int i = tid; i < HALF_N; i += NT) outr[i] = yb[SKEW(i)];
}

// ---------------------------------------------------------------------------
extern "C" void kernel_launch(void* const* d_in, const int* in_sizes, int n_in,
                              void* d_out, int out_size) {
    const float* x;
    const float* kern;
    if (in_sizes[0] == NROWS * L_SEQ) {
        x    = (const float*)d_in[0];
        kern = (const float*)d_in[1];
    } else {
        x    = (const float*)d_in[1];
        kern = (const float*)d_in[0];
    }
    float* out = (float*)d_out;

    cudaFuncSetAttribute(kspec_kernel, cudaFuncAttributeMaxDynamicSharedMemorySize, SMEM_BYTES);
    cudaFuncSetAttribute(conv_kernel,  cudaFuncAttributeMaxDynamicSharedMemorySize, SMEM_BYTES);

    kspec_kernel<<<NCHAN, NT, SMEM_BYTES>>>(kern);
    conv_kernel<<<NROWS, NT, SMEM_BYTES>>>(x, out);
}

// round 6
// speedup vs baseline: 2.4575x; 1.2832x over previous
#include <cuda_runtime.h>
#include <math.h>

// out[b,c,:] = irfft( rfft(x,16384) * Kspec[c], 16384 )[:8192]
// rfft(16384) via 8192-pt complex FFT of z[n] = x[2n] + i x[2n+1].
// conv: fwd radix [8,8,8,8,(2)], inv radix [(2),8,8,8,8]; the fwd r2 finisher,
// spectral multiply and inv r2 opener are fused into one register pass; the
// global load fuses into fwd stage-1 and the global store into inv stage-5.

#define N_FFT   8192
#define HALF_N  4096
#define NT      1024
#define L_SEQ   8192
#define NCHAN   256
#define NROWS   2048

#define BUF_PAD 8704
#define SKEW(a) ((a) + ((a) >> 4))
#define TWT     1024

__device__ float2 g_kspec[(size_t)NCHAN * (N_FFT + 1)];

__device__ __forceinline__ float2 cmul(float2 a, float2 b) {
    return make_float2(a.x * b.x - a.y * b.y, a.x * b.y + a.y * b.x);
}
__device__ __forceinline__ float2 cadd(float2 a, float2 b) { return make_float2(a.x + b.x, a.y + b.y); }
__device__ __forceinline__ float2 csub(float2 a, float2 b) { return make_float2(a.x - b.x, a.y - b.y); }

template <int INV>
__device__ __forceinline__ void dft8(float2* v) {
    const float u = 0.70710678118654752f;
    float2 apc = cadd(v[0], v[4]), amc = csub(v[0], v[4]);
    float2 bpd = cadd(v[2], v[6]), bmd = csub(v[2], v[6]);
    float2 E0 = cadd(apc, bpd), E2 = csub(apc, bpd), E1, E3;
    if (!INV) { E1 = make_float2(amc.x + bmd.y, amc.y - bmd.x); E3 = make_float2(amc.x - bmd.y, amc.y + bmd.x); }
    else      { E1 = make_float2(amc.x - bmd.y, amc.y + bmd.x); E3 = make_float2(amc.x + bmd.y, amc.y - bmd.x); }
    apc = cadd(v[1], v[5]); amc = csub(v[1], v[5]);
    bpd = cadd(v[3], v[7]); bmd = csub(v[3], v[7]);
    float2 O0 = cadd(apc, bpd), O2 = csub(apc, bpd), O1, O3;
    if (!INV) { O1 = make_float2(amc.x + bmd.y, amc.y - bmd.x); O3 = make_float2(amc.x - bmd.y, amc.y + bmd.x); }
    else      { O1 = make_float2(amc.x - bmd.y, amc.y + bmd.x); O3 = make_float2(amc.x + bmd.y, amc.y - bmd.x); }
    float2 T1, T2, T3;
    if (!INV) {
        T1 = make_float2(u * (O1.x + O1.y), u * (O1.y - O1.x));
        T2 = make_float2(O2.y, -O2.x);
        T3 = make_float2(u * (O3.y - O3.x), -u * (O3.x + O3.y));
    } else {
        T1 = make_float2(u * (O1.x - O1.y), u * (O1.x + O1.y));
        T2 = make_float2(-O2.y, O2.x);
        T3 = make_float2(-u * (O3.x + O3.y), u * (O3.x - O3.y));
    }
    v[0] = cadd(E0, O0); v[4] = csub(E0, O0);
    v[1] = cadd(E1, T1); v[5] = csub(E1, T1);
    v[2] = cadd(E2, T2); v[6] = csub(E2, T2);
    v[3] = cadd(E3, T3); v[7] = csub(E3, T3);
}

// generic SMEM radix-8 Stockham stage (one butterfly per thread)
template <int INV>
__device__ __forceinline__ void stage_r8(const float2* __restrict__ x, float2* __restrict__ y,
                                         const float2* __restrict__ tw1,
                                         const float2* __restrict__ tw2,
                                         const float2* __restrict__ tw4, int s, int tid) {
    const int q = tid & (s - 1);
    const int e = tid - q;
    float2 v[8];
#pragma unroll
    for (int j = 0; j < 8; j++) v[j] = x[SKEW(tid + (j << 10))];
    dft8<INV>(v);
    float2 w1 = tw1[e], w2 = tw2[e], w4 = tw4[e];
    if (INV) { w1.y = -w1.y; w2.y = -w2.y; w4.y = -w4.y; }
    float2 w3 = cmul(w1, w2), w5 = cmul(w1, w4), w6 = cmul(w2, w4), w7 = cmul(w3, w4);
    const int o = q + (e << 3);
    y[SKEW(o)]       = v[0];
    y[SKEW(o + s)]   = cmul(w1, v[1]);
    y[SKEW(o + 2*s)] = cmul(w2, v[2]);
    y[SKEW(o + 3*s)] = cmul(w3, v[3]);
    y[SKEW(o + 4*s)] = cmul(w4, v[4]);
    y[SKEW(o + 5*s)] = cmul(w5, v[5]);
    y[SKEW(o + 6*s)] = cmul(w6, v[6]);
    y[SKEW(o + 7*s)] = cmul(w7, v[7]);
}

__device__ __forceinline__ void fill_tw(float2* tw1, float2* tw2, float2* tw4, int tid) {
#pragma unroll 1
    for (int j = tid; j < TWT; j += NT) {
        float s, c;
        sincospif((float)j * (1.0f / 4096.0f), &s, &c);
        tw1[j] = make_float2(c, -s);
        sincospif((float)j * (1.0f / 2048.0f), &s, &c);
        tw2[j] = make_float2(c, -s);
        sincospif((float)j * (1.0f / 1024.0f), &s, &c);
        tw4[j] = make_float2(c, -s);
    }
}

__device__ __forceinline__ float2 efac(int k) {   // e^{-i pi k/8192}
    float s, c;
    sincospif((float)k * (1.0f / 8192.0f), &s, &c);
    return make_float2(c, -s);
}
__device__ __forceinline__ float2 winv(int i) {   // conj(W_8192^i) = e^{+2 pi i i/8192}
    float s, c;
    sincospif((float)i * (1.0f / 4096.0f), &s, &c);
    return make_float2(c, s);
}

// spectral pair: from packed Z[k], Z[8192-k] and K[k], K[8192-k] produce W[k], W[8192-k]
__device__ __forceinline__ void spec_pair(float2 Zk, float2 Zn, float2 Kk, float2 Kn, int k,
                                          float2* Wk, float2* Wn) {
    float2 A = make_float2(0.5f * (Zk.x + Zn.x), 0.5f * (Zk.y - Zn.y));
    float2 D = make_float2(0.5f * (Zk.x - Zn.x), 0.5f * (Zk.y + Zn.y));
    float2 B = make_float2(D.y, -D.x);
    float2 E = efac(k);
    float2 EB = cmul(E, B);
    float2 Xk = make_float2(A.x + EB.x, A.y + EB.y);
    float2 Xn = make_float2(A.x - EB.x, -(A.y - EB.y));
    float2 Yk = cmul(Xk, Kk);
    float2 Yn = cmul(Xn, Kn);
    float2 Ay = make_float2(0.5f * (Yk.x + Yn.x), 0.5f * (Yk.y - Yn.y));
    float2 Dy = make_float2(0.5f * (Yk.x - Yn.x), 0.5f * (Yk.y + Yn.y));
    float2 Ec = make_float2(E.x, -E.y);
    float2 By = cmul(Ec, Dy);
    *Wk = make_float2(Ay.x - By.y,  Ay.y + By.x);
    *Wn = make_float2(Ay.x + By.y, -Ay.y + By.x);
}

__device__ __forceinline__ float smooth_squash(const float* rk, int i) {
    float ssum = 0.f;
#pragma unroll
    for (int d = -3; d <= 3; d++) {
        int j = i + d;
        j = (j < 0) ? -j : j;
        j = (j > L_SEQ - 1) ? (2 * (L_SEQ - 1) - j) : j;
        ssum += rk[j];
    }
    float v = ssum * (1.0f / 7.0f);
    float a = fabsf(v) - 0.003f;
    return (a > 0.f) ? copysignf(a, v) : 0.f;
}

// smem: b0[BUF_PAD] | b1[BUF_PAD] | tw1 | tw2 | tw4
#define SMEM_BYTES ((2 * BUF_PAD + 3 * TWT) * (int)sizeof(float2))

// ---------------------------------------------------------------------------
// kspec (unchanged structure: full fwd FFT with finisher, spectrum to global)
// ---------------------------------------------------------------------------
__global__ void __launch_bounds__(NT, 1) kspec_kernel(const float* __restrict__ kern) {
    extern __shared__ float2 sm2[];
    float2* b0  = sm2;
    float2* b1  = sm2 + BUF_PAD;
    float2* tw1 = sm2 + 2 * BUF_PAD;
    float2* tw2 = tw1 + TWT;
    float2* tw4 = tw2 + TWT;
    float*  rk  = (float*)b1;

    const int c   = blockIdx.x;
    const int tid = threadIdx.x;
    const float* kr = kern + (size_t)c * L_SEQ;

    for (int i = tid; i < L_SEQ; i += NT) rk[i] = kr[i];
    fill_tw(tw1, tw2, tw4, tid);
    __syncthreads();

    for (int n = tid; n < HALF_N; n += NT) {
        float v0 = smooth_squash(rk, 2 * n);
        float v1 = smooth_squash(rk, 2 * n + 1);
        b0[SKEW(n)] = make_float2(v0, v1);
    }
    for (int n = HALF_N + tid; n < N_FFT; n += NT)
        b0[SKEW(n)] = make_float2(0.f, 0.f);
    __syncthreads();

    stage_r8<0>(b0, b1, tw1, tw2, tw4, 1, tid);   __syncthreads();
    stage_r8<0>(b1, b0, tw1, tw2, tw4, 8, tid);   __syncthreads();
    stage_r8<0>(b0, b1, tw1, tw2, tw4, 64, tid);  __syncthreads();
    stage_r8<0>(b1, b0, tw1, tw2, tw4, 512, tid); __syncthreads();
#pragma unroll
    for (int u = 0; u < 4; u++) {                 // r2 finisher -> b1 natural
        const int q = tid + (u << 10);
        float2 a = b0[SKEW(q)];
        float2 b = b0[SKEW(q + 4096)];
        b1[SKEW(q)]        = cadd(a, b);
        b1[SKEW(q + 4096)] = csub(a, b);
    }
    __syncthreads();

    float2* Kc = g_kspec + (size_t)c * (N_FFT + 1);
    const float inv = 1.0f / (float)N_FFT;
    for (int k = tid; k <= HALF_N; k += NT) {
        if (k == 0) {
            float2 Z0 = b1[SKEW(0)];
            Kc[0]     = make_float2((Z0.x + Z0.y) * inv, 0.f);
            Kc[N_FFT] = make_float2((Z0.x - Z0.y) * inv, 0.f);
        } else {
            float2 Zk = b1[SKEW(k)];
            float2 Zn = b1[SKEW(N_FFT - k)];
            float2 A = make_float2(0.5f * (Zk.x + Zn.x), 0.5f * (Zk.y - Zn.y));
            float2 D = make_float2(0.5f * (Zk.x - Zn.x), 0.5f * (Zk.y + Zn.y));
            float2 B = make_float2(D.y, -D.x);
            float2 E = efac(k);
            float2 EB = cmul(E, B);
            float2 Xk = make_float2(A.x + EB.x, A.y + EB.y);
            float2 Xn = make_float2(A.x - EB.x, -(A.y - EB.y));
            Kc[k]         = make_float2(Xk.x * inv, Xk.y * inv);
            Kc[N_FFT - k] = make_float2(Xn.x * inv, Xn.y * inv);
        }
    }
}

// ---------------------------------------------------------------------------
// conv: one CTA per (b,c) row, fused seams.
// ---------------------------------------------------------------------------
__global__ void __launch_bounds__(NT, 1) conv_kernel(const float* __restrict__ x,
                                                     float* __restrict__ out) {
    extern __shared__ float2 sm2[];
    float2* b0  = sm2;
    float2* b1  = sm2 + BUF_PAD;
    float2* tw1 = sm2 + 2 * BUF_PAD;
    float2* tw2 = tw1 + TWT;
    float2* tw4 = tw2 + TWT;

    const int row = blockIdx.x;
    const int c   = row & (NCHAN - 1);
    const int tid = threadIdx.x;
    const float2* xr = (const float2*)(x + (size_t)row * L_SEQ);

    fill_tw(tw1, tw2, tw4, tid);
    __syncthreads();

    // fwd stage 1 (s=1): read global directly (upper half zero), write b0
    {
        float2 v[8];
#pragma unroll
        for (int j = 0; j < 8; j++)
            v[j] = (j < 4) ? xr[tid + (j << 10)] : make_float2(0.f, 0.f);
        dft8<0>(v);
        const int e = tid;
        float2 w1 = tw1[e], w2 = tw2[e], w4 = tw4[e];
        float2 w3 = cmul(w1, w2), w5 = cmul(w1, w4), w6 = cmul(w2, w4), w7 = cmul(w3, w4);
        const int o = tid << 3;
        b0[SKEW(o)]     = v[0];
        b0[SKEW(o + 1)] = cmul(w1, v[1]);
        b0[SKEW(o + 2)] = cmul(w2, v[2]);
        b0[SKEW(o + 3)] = cmul(w3, v[3]);
        b0[SKEW(o + 4)] = cmul(w4, v[4]);
        b0[SKEW(o + 5)] = cmul(w5, v[5]);
        b0[SKEW(o + 6)] = cmul(w6, v[6]);
        b0[SKEW(o + 7)] = cmul(w7, v[7]);
    }
    __syncthreads();
    stage_r8<0>(b0, b1, tw1, tw2, tw4, 8, tid);   __syncthreads();
    stage_r8<0>(b1, b0, tw1, tw2, tw4, 64, tid);  __syncthreads();
    stage_r8<0>(b0, b1, tw1, tw2, tw4, 512, tid); __syncthreads();
    // P = b1 (pre-finisher)

    // fused: fwd r2 finisher + spectral multiply + inv r2 opener -> b0
    const float2* Kc = g_kspec + (size_t)c * (N_FFT + 1);
#pragma unroll 1
    for (int u = 0; u < 2; u++) {
        const int q = tid + (u << 10);            // [0,2048)
        if (q == 0) {
            float2 Pa = b1[SKEW(0)],    Pb = b1[SKEW(4096)];
            float2 Pc = b1[SKEW(2048)], Pd = b1[SKEW(6144)];
            float2 Z0 = cadd(Pa, Pb), Z4 = csub(Pa, Pb);
            float2 Z2 = cadd(Pc, Pd), Z6 = csub(Pc, Pd);
            // k = 0 (DC + Nyquist of the 16384-transform)
            float X0 = Z0.x + Z0.y, XN = Z0.x - Z0.y;
            float2 K0 = Kc[0], KN = Kc[N_FFT];
            float2 Y0 = make_float2(X0 * K0.x, X0 * K0.y);
            float2 YN = make_float2(XN * KN.x, XN * KN.y);
            float2 Ay = make_float2(0.5f * (Y0.x + YN.x), 0.5f * (Y0.y - YN.y));
            float2 Dy = make_float2(0.5f * (Y0.x - YN.x), 0.5f * (Y0.y + YN.y));
            float2 W0 = make_float2(Ay.x - Dy.y, Ay.y + Dy.x);
            // k = 4096 (self-pair)
            float2 W4, Wdum;
            spec_pair(Z4, Z4, Kc[4096], Kc[4096], 4096, &W4, &Wdum);
            // k = 2048 pair (2048, 6144)
            float2 W2, W6;
            spec_pair(Z2, Z6, Kc[2048], Kc[6144], 2048, &W2, &W6);
            // inverse r2: i=0 and i=2048
            b0[SKEW(0)] = cadd(W0, W4);
            b0[SKEW(1)] = csub(W0, W4);
            b0[SKEW(4096)] = cadd(W2, W6);
            float2 t = csub(W2, W6);               // * conj(W^2048) = i
            b0[SKEW(4097)] = make_float2(-t.y, t.x);
        } else {
            const int r = 4096 - q;
            float2 Pa = b1[SKEW(q)], Pb = b1[SKEW(q + 4096)];
            float2 Pc = b1[SKEW(r)], Pd = b1[SKEW(r + 4096)];
            float2 Zq  = cadd(Pa, Pb), Zq4 = csub(Pa, Pb);   // Z[q], Z[q+4096]
            float2 Zr  = cadd(Pc, Pd), Znq = csub(Pc, Pd);   // Z[4096-q], Z[8192-q]
            float2 Wq, Wnq, Wr, Wpq;
            spec_pair(Zq, Znq, Kc[q], Kc[N_FFT - q], q, &Wq, &Wnq);           // k=q
            spec_pair(Zr, Zq4, Kc[r], Kc[4096 + q], r, &Wr, &Wpq);            // k=4096-q
            // inverse r2: i=q uses W[q], W[q+4096]=Wpq ; i=r uses W[r], W[8192-q]=Wnq
            b0[SKEW(2 * q)]     = cadd(Wq, Wpq);
            b0[SKEW(2 * q + 1)] = cmul(csub(Wq, Wpq), winv(q));
            b0[SKEW(2 * r)]     = cadd(Wr, Wnq);
            b0[SKEW(2 * r + 1)] = cmul(csub(Wr, Wnq), winv(r));
        }
    }
    __syncthreads();

    // inverse radix-8 stages: s = 2, 16, 128
    stage_r8<1>(b0, b1, tw1, tw2, tw4, 2, tid);   __syncthreads();
    stage_r8<1>(b1, b0, tw1, tw2, tw4, 16, tid);  __syncthreads();
    stage_r8<1>(b0, b1, tw1, tw2, tw4, 128, tid); __syncthreads();

    // final inverse stage s=1024 (p=0, twiddle-free): write first half to global
    {
        float2 v[8];
#pragma unroll
        for (int j = 0; j < 8; j++) v[j] = b1[SKEW(tid + (j << 10))];
        dft8<1>(v);
        float2* outr = (float2*)(out + (size_t)row * L_SEQ);
#pragma unroll
        for (int j = 0; j < 4; j++) outr[tid + (j << 10)] = v[j];
    }
}

// ---------------------------------------------------------------------------
extern "C" void kernel_launch(void* const* d_in, const int* in_sizes, int n_in,
                              void* d_out, int out_size) {
    const float* x;
    const float* kern;
    if (in_sizes[0] == NROWS * L_SEQ) {
        x    = (const float*)d_in[0];
        kern = (const float*)d_in[1];
    } else {
        x    = (const float*)d_in[1];
        kern = (const float*)d_in[0];
    }
    float* out = (float*)d_out;

    cudaFuncSetAttribute(kspec_kernel, cudaFuncAttributeMaxDynamicSharedMemorySize, SMEM_BYTES);
    cudaFuncSetAttribute(conv_kernel,  cudaFuncAttributeMaxDynamicSharedMemorySize, SMEM_BYTES);

    kspec_kernel<<<NCHAN, NT, SMEM_BYTES>>>(kern);
    conv_kernel<<<NROWS, NT, SMEM_BYTES>>>(x, out);
}

// round 7
// speedup vs baseline: 2.5405x; 1.0337x over previous
#include <cuda_runtime.h>
#include <math.h>

// out[b,c,:] = irfft( rfft(x,16384) * Kspec[c], 16384 )[:8192]
// rfft(16384) via 8192-pt complex FFT of z[n] = x[2n] + i x[2n+1].
// fwd radix [8,8,8,8,(2)], inv radix [(2),8,8,8,8]; r2 stages + spectral
// multiply fused into register passes; global I/O fused into first/last stages.

#define N_FFT   8192
#define HALF_N  4096
#define NT      1024
#define L_SEQ   8192
#define NCHAN   256
#define NROWS   2048

#define BUF_PAD 8704
#define SKEW(a) ((a) + ((a) >> 4))
#define TWT     1024

__device__ float2 g_kspec[(size_t)NCHAN * (N_FFT + 1)];

__device__ __forceinline__ float2 cmul(float2 a, float2 b) {
    return make_float2(a.x * b.x - a.y * b.y, a.x * b.y + a.y * b.x);
}
__device__ __forceinline__ float2 cmulc(float2 a, float2 b) {   // a * conj(b)
    return make_float2(a.x * b.x + a.y * b.y, a.y * b.x - a.x * b.y);
}
__device__ __forceinline__ float2 cadd(float2 a, float2 b) { return make_float2(a.x + b.x, a.y + b.y); }
__device__ __forceinline__ float2 csub(float2 a, float2 b) { return make_float2(a.x - b.x, a.y - b.y); }

template <int INV>
__device__ __forceinline__ void dft8(float2* v) {
    const float u = 0.70710678118654752f;
    float2 apc = cadd(v[0], v[4]), amc = csub(v[0], v[4]);
    float2 bpd = cadd(v[2], v[6]), bmd = csub(v[2], v[6]);
    float2 E0 = cadd(apc, bpd), E2 = csub(apc, bpd), E1, E3;
    if (!INV) { E1 = make_float2(amc.x + bmd.y, amc.y - bmd.x); E3 = make_float2(amc.x - bmd.y, amc.y + bmd.x); }
    else      { E1 = make_float2(amc.x - bmd.y, amc.y + bmd.x); E3 = make_float2(amc.x + bmd.y, amc.y - bmd.x); }
    apc = cadd(v[1], v[5]); amc = csub(v[1], v[5]);
    bpd = cadd(v[3], v[7]); bmd = csub(v[3], v[7]);
    float2 O0 = cadd(apc, bpd), O2 = csub(apc, bpd), O1, O3;
    if (!INV) { O1 = make_float2(amc.x + bmd.y, amc.y - bmd.x); O3 = make_float2(amc.x - bmd.y, amc.y + bmd.x); }
    else      { O1 = make_float2(amc.x - bmd.y, amc.y + bmd.x); O3 = make_float2(amc.x + bmd.y, amc.y - bmd.x); }
    float2 T1, T2, T3;
    if (!INV) {
        T1 = make_float2(u * (O1.x + O1.y), u * (O1.y - O1.x));
        T2 = make_float2(O2.y, -O2.x);
        T3 = make_float2(u * (O3.y - O3.x), -u * (O3.x + O3.y));
    } else {
        T1 = make_float2(u * (O1.x - O1.y), u * (O1.x + O1.y));
        T2 = make_float2(-O2.y, O2.x);
        T3 = make_float2(-u * (O3.x + O3.y), u * (O3.x - O3.y));
    }
    v[0] = cadd(E0, O0); v[4] = csub(E0, O0);
    v[1] = cadd(E1, T1); v[5] = csub(E1, T1);
    v[2] = cadd(E2, T2); v[6] = csub(E2, T2);
    v[3] = cadd(E3, T3); v[7] = csub(E3, T3);
}

// forward dft8 with v[4..7] == 0 implied (zero-padded upper half)
__device__ __forceinline__ void dft8_half(float2* v) {
    const float u = 0.70710678118654752f;
    float2 E0 = cadd(v[0], v[2]), E2 = csub(v[0], v[2]);
    float2 E1 = make_float2(v[0].x + v[2].y, v[0].y - v[2].x);
    float2 E3 = make_float2(v[0].x - v[2].y, v[0].y + v[2].x);
    float2 O0 = cadd(v[1], v[3]), O2 = csub(v[1], v[3]);
    float2 O1 = make_float2(v[1].x + v[3].y, v[1].y - v[3].x);
    float2 O3 = make_float2(v[1].x - v[3].y, v[1].y + v[3].x);
    float2 T1 = make_float2(u * (O1.x + O1.y), u * (O1.y - O1.x));
    float2 T2 = make_float2(O2.y, -O2.x);
    float2 T3 = make_float2(u * (O3.y - O3.x), -u * (O3.x + O3.y));
    v[0] = cadd(E0, O0); v[4] = csub(E0, O0);
    v[1] = cadd(E1, T1); v[5] = csub(E1, T1);
    v[2] = cadd(E2, T2); v[6] = csub(E2, T2);
    v[3] = cadd(E3, T3); v[7] = csub(E3, T3);
}

template <int INV>
__device__ __forceinline__ void stage_r8(const float2* __restrict__ x, float2* __restrict__ y,
                                         const float2* __restrict__ tw1,
                                         const float2* __restrict__ tw2,
                                         const float2* __restrict__ tw4, int s, int tid) {
    const int q = tid & (s - 1);
    const int e = tid - q;
    float2 v[8];
#pragma unroll
    for (int j = 0; j < 8; j++) v[j] = x[SKEW(tid + (j << 10))];
    dft8<INV>(v);
    float2 w1 = tw1[e], w2 = tw2[e], w4 = tw4[e];
    if (INV) { w1.y = -w1.y; w2.y = -w2.y; w4.y = -w4.y; }
    float2 w3 = cmul(w1, w2), w5 = cmul(w1, w4), w6 = cmul(w2, w4), w7 = cmul(w3, w4);
    const int o = q + (e << 3);
    y[SKEW(o)]       = v[0];
    y[SKEW(o + s)]   = cmul(w1, v[1]);
    y[SKEW(o + 2*s)] = cmul(w2, v[2]);
    y[SKEW(o + 3*s)] = cmul(w3, v[3]);
    y[SKEW(o + 4*s)] = cmul(w4, v[4]);
    y[SKEW(o + 5*s)] = cmul(w5, v[5]);
    y[SKEW(o + 6*s)] = cmul(w6, v[6]);
    y[SKEW(o + 7*s)] = cmul(w7, v[7]);
}

// twiddle-write for the fused (register-input) stage-1, s = 1
__device__ __forceinline__ void stage1_write(float2* __restrict__ y, const float2* v,
                                             const float2* __restrict__ tw1,
                                             const float2* __restrict__ tw2,
                                             const float2* __restrict__ tw4, int tid) {
    float2 w1 = tw1[tid], w2 = tw2[tid], w4 = tw4[tid];
    float2 w3 = cmul(w1, w2), w5 = cmul(w1, w4), w6 = cmul(w2, w4), w7 = cmul(w3, w4);
    const int o = tid << 3;
    y[SKEW(o)]     = v[0];
    y[SKEW(o + 1)] = cmul(w1, v[1]);
    y[SKEW(o + 2)] = cmul(w2, v[2]);
    y[SKEW(o + 3)] = cmul(w3, v[3]);
    y[SKEW(o + 4)] = cmul(w4, v[4]);
    y[SKEW(o + 5)] = cmul(w5, v[5]);
    y[SKEW(o + 6)] = cmul(w6, v[6]);
    y[SKEW(o + 7)] = cmul(w7, v[7]);
}

// fill twiddle tables: tw1=W^j, tw2=W^2j, tw4=W^4j (j<1024); twh=e^{-i pi k/8192} (k<4096)
__device__ __forceinline__ void fill_tw(float2* tw1, float2* tw2, float2* tw4,
                                        float2* twh, int tid) {
#pragma unroll 1
    for (int j = tid; j < TWT; j += NT) {
        float s, c;
        sincospif((float)j * (1.0f / 4096.0f), &s, &c);
        tw1[j] = make_float2(c, -s);
        sincospif((float)j * (1.0f / 2048.0f), &s, &c);
        tw2[j] = make_float2(c, -s);
        sincospif((float)j * (1.0f / 1024.0f), &s, &c);
        tw4[j] = make_float2(c, -s);
    }
#pragma unroll 1
    for (int k = tid; k < HALF_N; k += NT) {
        float s, c;
        sincospif((float)k * (1.0f / 8192.0f), &s, &c);
        twh[k] = make_float2(c, -s);
    }
}

// unpack pair: from Z[k], Z[8192-k] and E=e^{-i pi k/8192} produce X[k], X[8192-k]
__device__ __forceinline__ void unpack_pair(float2 Zk, float2 Zn, float2 E,
                                            float2* Xk, float2* Xn) {
    float2 A = make_float2(0.5f * (Zk.x + Zn.x), 0.5f * (Zk.y - Zn.y));
    float2 D = make_float2(0.5f * (Zk.x - Zn.x), 0.5f * (Zk.y + Zn.y));
    float2 B = make_float2(D.y, -D.x);
    float2 EB = cmul(E, B);
    *Xk = make_float2(A.x + EB.x, A.y + EB.y);
    *Xn = make_float2(A.x - EB.x, -(A.y - EB.y));
}

// spectral pair multiply + repack
__device__ __forceinline__ void spec_pair(float2 Zk, float2 Zn, float2 Kk, float2 Kn,
                                          float2 E, float2* Wk, float2* Wn) {
    float2 Xk, Xn;
    unpack_pair(Zk, Zn, E, &Xk, &Xn);
    float2 Yk = cmul(Xk, Kk);
    float2 Yn = cmul(Xn, Kn);
    float2 Ay = make_float2(0.5f * (Yk.x + Yn.x), 0.5f * (Yk.y - Yn.y));
    float2 Dy = make_float2(0.5f * (Yk.x - Yn.x), 0.5f * (Yk.y + Yn.y));
    float2 By = cmulc(Dy, E);
    *Wk = make_float2(Ay.x - By.y,  Ay.y + By.x);
    *Wn = make_float2(Ay.x + By.y, -Ay.y + By.x);
}

__device__ __forceinline__ float smooth_squash(const float* rk, int i) {
    float ssum = 0.f;
#pragma unroll
    for (int d = -3; d <= 3; d++) {
        int j = i + d;
        j = (j < 0) ? -j : j;
        j = (j > L_SEQ - 1) ? (2 * (L_SEQ - 1) - j) : j;
        ssum += rk[j];
    }
    float v = ssum * (1.0f / 7.0f);
    float a = fabsf(v) - 0.003f;
    return (a > 0.f) ? copysignf(a, v) : 0.f;
}

// smem: b0[BUF_PAD] | b1[BUF_PAD] | tw1 | tw2 | tw4 | twh[4096]
#define SMEM_BYTES ((2 * BUF_PAD + 3 * TWT + HALF_N) * (int)sizeof(float2))

// ---------------------------------------------------------------------------
// kspec: fused smooth/squash->stage1, 3 SMEM stages, fused finisher+store
// ---------------------------------------------------------------------------
__global__ void __launch_bounds__(NT, 1) kspec_kernel(const float* __restrict__ kern) {
    extern __shared__ float2 sm2[];
    float2* b0  = sm2;
    float2* b1  = sm2 + BUF_PAD;
    float2* tw1 = sm2 + 2 * BUF_PAD;
    float2* tw2 = tw1 + TWT;
    float2* tw4 = tw2 + TWT;
    float2* twh = tw4 + TWT;
    float*  rk  = (float*)b1;

    const int c   = blockIdx.x;
    const int tid = threadIdx.x;
    const float* kr = kern + (size_t)c * L_SEQ;

    for (int i = tid; i < L_SEQ; i += NT) rk[i] = kr[i];
    fill_tw(tw1, tw2, tw4, twh, tid);
    __syncthreads();

    // fused stage 1: compute packed squash(smooth) samples in registers
    {
        float2 v[8];
#pragma unroll
        for (int j = 0; j < 4; j++) {
            const int n = tid + (j << 10);
            v[j] = make_float2(smooth_squash(rk, 2 * n), smooth_squash(rk, 2 * n + 1));
        }
        dft8_half(v);
        stage1_write(b0, v, tw1, tw2, tw4, tid);
    }
    __syncthreads();
    stage_r8<0>(b0, b1, tw1, tw2, tw4, 8, tid);   __syncthreads();
    stage_r8<0>(b1, b0, tw1, tw2, tw4, 64, tid);  __syncthreads();
    stage_r8<0>(b0, b1, tw1, tw2, tw4, 512, tid); __syncthreads();
    // P = b1 (pre-finisher)

    // fused r2 finisher + unpack + store (scaled by 1/N)
    float2* Kc = g_kspec + (size_t)c * (N_FFT + 1);
    const float inv = 1.0f / (float)N_FFT;
#pragma unroll 1
    for (int u = 0; u < 2; u++) {
        const int q = tid + (u << 10);
        if (q == 0) {
            float2 Pa = b1[SKEW(0)],    Pb = b1[SKEW(4096)];
            float2 Pc = b1[SKEW(2048)], Pd = b1[SKEW(6144)];
            float2 Z0 = cadd(Pa, Pb), Z4 = csub(Pa, Pb);
            float2 Z2 = cadd(Pc, Pd), Z6 = csub(Pc, Pd);
            Kc[0]      = make_float2((Z0.x + Z0.y) * inv, 0.f);
            Kc[N_FFT]  = make_float2((Z0.x - Z0.y) * inv, 0.f);
            Kc[4096]   = make_float2(Z4.x * inv, -Z4.y * inv);     // conj(Z[4096])
            float2 X2, X6;
            unpack_pair(Z2, Z6, twh[2048], &X2, &X6);
            Kc[2048] = make_float2(X2.x * inv, X2.y * inv);
            Kc[6144] = make_float2(X6.x * inv, X6.y * inv);
        } else {
            const int r = 4096 - q;
            float2 Pa = b1[SKEW(q)], Pb = b1[SKEW(q + 4096)];
            float2 Pc = b1[SKEW(r)], Pd = b1[SKEW(r + 4096)];
            float2 Zq  = cadd(Pa, Pb), Zq4 = csub(Pa, Pb);
            float2 Zr  = cadd(Pc, Pd), Znq = csub(Pc, Pd);
            float2 Xq, Xnq, Xr, Xpq;
            unpack_pair(Zq, Znq, twh[q], &Xq, &Xnq);
            unpack_pair(Zr, Zq4, twh[r], &Xr, &Xpq);
            Kc[q]          = make_float2(Xq.x * inv,  Xq.y * inv);
            Kc[N_FFT - q]  = make_float2(Xnq.x * inv, Xnq.y * inv);
            Kc[r]          = make_float2(Xr.x * inv,  Xr.y * inv);
            Kc[4096 + q]   = make_float2(Xpq.x * inv, Xpq.y * inv);
        }
    }
}

// ---------------------------------------------------------------------------
// conv: one CTA per (b,c) row
// ---------------------------------------------------------------------------
__global__ void __launch_bounds__(NT, 1) conv_kernel(const float* __restrict__ x,
                                                     float* __restrict__ out) {
    extern __shared__ float2 sm2[];
    float2* b0  = sm2;
    float2* b1  = sm2 + BUF_PAD;
    float2* tw1 = sm2 + 2 * BUF_PAD;
    float2* tw2 = tw1 + TWT;
    float2* tw4 = tw2 + TWT;
    float2* twh = tw4 + TWT;

    const int row = blockIdx.x;
    const int c   = row & (NCHAN - 1);
    const int tid = threadIdx.x;
    const float2* xr = (const float2*)(x + (size_t)row * L_SEQ);

    fill_tw(tw1, tw2, tw4, twh, tid);
    __syncthreads();

    // fwd stage 1: global read fused (upper half zero)
    {
        float2 v[8];
#pragma unroll
        for (int j = 0; j < 4; j++) v[j] = xr[tid + (j << 10)];
        dft8_half(v);
        stage1_write(b0, v, tw1, tw2, tw4, tid);
    }
    __syncthreads();
    stage_r8<0>(b0, b1, tw1, tw2, tw4, 8, tid);   __syncthreads();
    stage_r8<0>(b1, b0, tw1, tw2, tw4, 64, tid);  __syncthreads();
    stage_r8<0>(b0, b1, tw1, tw2, tw4, 512, tid); __syncthreads();
    // P = b1

    // fused: fwd r2 finisher + spectral multiply + inv r2 opener -> b0
    const float2* Kc = g_kspec + (size_t)c * (N_FFT + 1);
#pragma unroll 1
    for (int u = 0; u < 2; u++) {
        const int q = tid + (u << 10);
        if (q == 0) {
            float2 Pa = b1[SKEW(0)],    Pb = b1[SKEW(4096)];
            float2 Pc = b1[SKEW(2048)], Pd = b1[SKEW(6144)];
            float2 Z0 = cadd(Pa, Pb), Z4 = csub(Pa, Pb);
            float2 Z2 = cadd(Pc, Pd), Z6 = csub(Pc, Pd);
            float X0 = Z0.x + Z0.y, XN = Z0.x - Z0.y;
            float2 K0 = Kc[0], KN = Kc[N_FFT];
            float2 Y0 = make_float2(X0 * K0.x, X0 * K0.y);
            float2 YN = make_float2(XN * KN.x, XN * KN.y);
            float2 Ay = make_float2(0.5f * (Y0.x + YN.x), 0.5f * (Y0.y - YN.y));
            float2 Dy = make_float2(0.5f * (Y0.x - YN.x), 0.5f * (Y0.y + YN.y));
            float2 W0 = make_float2(Ay.x - Dy.y, Ay.y + Dy.x);
            float2 W4, Wdum;
            spec_pair(Z4, Z4, Kc[4096], Kc[4096], make_float2(0.f, -1.f), &W4, &Wdum);
            float2 W2, W6;
            spec_pair(Z2, Z6, Kc[2048], Kc[6144], twh[2048], &W2, &W6);
            b0[SKEW(0)] = cadd(W0, W4);
            b0[SKEW(1)] = csub(W0, W4);
            b0[SKEW(4096)] = cadd(W2, W6);
            float2 t = csub(W2, W6);                   // * winv(2048) = i
            b0[SKEW(4097)] = make_float2(-t.y, t.x);
        } else {
            const int r = 4096 - q;
            float2 Pa = b1[SKEW(q)], Pb = b1[SKEW(q + 4096)];
            float2 Pc = b1[SKEW(r)], Pd = b1[SKEW(r + 4096)];
            float2 Zq  = cadd(Pa, Pb), Zq4 = csub(Pa, Pb);
            float2 Zr  = cadd(Pc, Pd), Znq = csub(Pc, Pd);
            float2 Eq = twh[q], Er = twh[r];
            float2 Wq, Wnq, Wr, Wpq;
            spec_pair(Zq, Znq, Kc[q], Kc[N_FFT - q], Eq, &Wq, &Wnq);
            spec_pair(Zr, Zq4, Kc[r], Kc[4096 + q], Er, &Wr, &Wpq);
            // winv(i) = conj(twh[i]^2)
            float2 wq = cmul(Eq, Eq), wr = cmul(Er, Er);
            b0[SKEW(2 * q)]     = cadd(Wq, Wpq);
            b0[SKEW(2 * q + 1)] = cmulc(csub(Wq, Wpq), wq);
            b0[SKEW(2 * r)]     = cadd(Wr, Wnq);
            b0[SKEW(2 * r + 1)] = cmulc(csub(Wr, Wnq), wr);
        }
    }
    __syncthreads();

    stage_r8<1>(b0, b1, tw1, tw2, tw4, 2, tid);   __syncthreads();
    stage_r8<1>(b1, b0, tw1, tw2, tw4, 16, tid);  __syncthreads();
    stage_r8<1>(b0, b1, tw1, tw2, tw4, 128, tid); __syncthreads();

    // final inverse stage s=1024 (twiddle-free): store first half to global
    {
        float2 v[8];
#pragma unroll
        for (int j = 0; j < 8; j++) v[j] = b1[SKEW(tid + (j << 10))];
        dft8<1>(v);
        float2* outr = (float2*)(out + (size_t)row * L_SEQ);
#pragma unroll
        for (int j = 0; j < 4; j++) outr[tid + (j << 10)] = v[j];
    }
}

// ---------------------------------------------------------------------------
extern "C" void kernel_launch(void* const* d_in, const int* in_sizes, int n_in,
                              void* d_out, int out_size) {
    const float* x;
    const float* kern;
    if (in_sizes[0] == NROWS * L_SEQ) {
        x    = (const float*)d_in[0];
        kern = (const float*)d_in[1];
    } else {
        x    = (const float*)d_in[1];
        kern = (const float*)d_in[0];
    }
    float* out = (float*)d_out;

    cudaFuncSetAttribute(kspec_kernel, cudaFuncAttributeMaxDynamicSharedMemorySize, SMEM_BYTES);
    cudaFuncSetAttribute(conv_kernel,  cudaFuncAttributeMaxDynamicSharedMemorySize, SMEM_BYTES);

    kspec_kernel<<<NCHAN, NT, SMEM_BYTES>>>(kern);
    conv_kernel<<<NROWS, NT, SMEM_BYTES>>>(x, out);
}